// round 3
// baseline (speedup 1.0000x reference)
#include <cuda_runtime.h>

#define NN 50000
#define EE 800000
#define DH 128
#define NH 8

// ---------------- device scratch (no cudaMalloc allowed) ----------------
__device__ float g_h[NN * DH];     // per-layer projected features h = x@W
__device__ float g_o[NN * DH];     // layer-1 output (activated)
__device__ float g_el[NN * NH];    // attention left logits
__device__ float g_er[NN * NH];    // attention right logits
__device__ int   g_off[NN + 1];    // CSR row offsets (by dst)
__device__ int   g_cur[NN];        // scatter cursors
__device__ int   g_cnt[NN];        // in-degree histogram
__device__ int   g_csr[EE];        // src node per CSR slot

// ---------------- CSR build ----------------
__global__ void zero_cnt_kernel() {
    int i = blockIdx.x * blockDim.x + threadIdx.x;
    if (i < NN) g_cnt[i] = 0;
}

__global__ void hist_kernel(const int* __restrict__ dst, int E) {
    int i = blockIdx.x * blockDim.x + threadIdx.x;
    if (i < E) atomicAdd(&g_cnt[dst[i]], 1);
}

// single-block chunked exclusive scan of g_cnt -> g_off, g_cur
__global__ void scan_kernel() {
    __shared__ int warp_sums[32];
    __shared__ int s_base;
    int tid = threadIdx.x;
    if (tid == 0) s_base = 0;
    __syncthreads();
    for (int c0 = 0; c0 < NN; c0 += 1024) {
        int i = c0 + tid;
        int v = (i < NN) ? g_cnt[i] : 0;
        // warp inclusive scan
        int x = v;
        #pragma unroll
        for (int o = 1; o < 32; o <<= 1) {
            int y = __shfl_up_sync(0xffffffffu, x, o);
            if ((tid & 31) >= o) x += y;
        }
        if ((tid & 31) == 31) warp_sums[tid >> 5] = x;
        __syncthreads();
        if (tid < 32) {
            int s = warp_sums[tid];
            #pragma unroll
            for (int o = 1; o < 32; o <<= 1) {
                int y = __shfl_up_sync(0xffffffffu, s, o);
                if (tid >= o) s += y;
            }
            warp_sums[tid] = s;  // inclusive warp-sum scan
        }
        __syncthreads();
        int warp_off = (tid >= 32) ? warp_sums[(tid >> 5) - 1] : 0;
        int incl = x + warp_off;
        int excl = incl - v;
        int base = s_base;
        if (i < NN) {
            g_off[i] = base + excl;
            g_cur[i] = base + excl;
        }
        __syncthreads();
        if (tid == 1023) s_base = base + incl;  // chunk total
        __syncthreads();
    }
    if (threadIdx.x == 0) g_off[NN] = s_base;
}

__global__ void scatter_kernel(const int* __restrict__ src,
                               const int* __restrict__ dst, int E) {
    int i = blockIdx.x * blockDim.x + threadIdx.x;
    if (i < E) {
        int p = atomicAdd(&g_cur[dst[i]], 1);
        g_csr[p] = src[i];
    }
}

// ---------------- GEMM + attention projections ----------------
// h[r][c] = sum_k x[r][k] * W[k][c];  el[r][hd] = sum_d h[r][hd*16+d]*al[hd][d]
// Block: 256 thr = 8 warps, 64 rows/block (8 rows/warp). Lane t owns cols 4t..4t+3.
__global__ __launch_bounds__(256) void gemm_attn(
    const float* __restrict__ x, const float* __restrict__ W,
    const float* __restrict__ al, const float* __restrict__ ar,
    float* __restrict__ h, float* __restrict__ el, float* __restrict__ er) {
    __shared__ float xs[64 * DH];  // 32 KB
    __shared__ float Ws[32 * DH];  // 16 KB
    int tid = threadIdx.x, lane = tid & 31, warp = tid >> 5;
    int row0 = blockIdx.x * 64;

    for (int idx = tid; idx < 64 * DH / 4; idx += 256) {
        int r = idx >> 5, c4 = idx & 31;
        float4 v = make_float4(0.f, 0.f, 0.f, 0.f);
        if (row0 + r < NN) v = ((const float4*)x)[(row0 + r) * 32 + c4];
        ((float4*)xs)[idx] = v;
    }

    float4 acc[8];
    #pragma unroll
    for (int r = 0; r < 8; r++) acc[r] = make_float4(0.f, 0.f, 0.f, 0.f);

    for (int kc = 0; kc < 4; kc++) {
        __syncthreads();
        for (int idx = tid; idx < 32 * DH / 4; idx += 256)
            ((float4*)Ws)[idx] = ((const float4*)W)[kc * 1024 + idx];
        __syncthreads();
        #pragma unroll 8
        for (int k = 0; k < 32; k++) {
            float4 w = ((float4*)Ws)[k * 32 + lane];
            #pragma unroll
            for (int r = 0; r < 8; r++) {
                float xv = xs[(warp * 8 + r) * DH + kc * 32 + k];
                acc[r].x = fmaf(xv, w.x, acc[r].x);
                acc[r].y = fmaf(xv, w.y, acc[r].y);
                acc[r].z = fmaf(xv, w.z, acc[r].z);
                acc[r].w = fmaf(xv, w.w, acc[r].w);
            }
        }
    }

    // al/ar flat [H*16]=128 floats; lane t covers exactly al_flat[4t..4t+3]
    float4 alv = ((const float4*)al)[lane];
    float4 arv = ((const float4*)ar)[lane];
    #pragma unroll
    for (int r = 0; r < 8; r++) {
        int row = row0 + warp * 8 + r;
        if (row < NN) {  // uniform per warp
            ((float4*)h)[row * 32 + lane] = acc[r];
            float pl = acc[r].x * alv.x + acc[r].y * alv.y + acc[r].z * alv.z + acc[r].w * alv.w;
            float pr = acc[r].x * arv.x + acc[r].y * arv.y + acc[r].z * arv.z + acc[r].w * arv.w;
            pl += __shfl_xor_sync(0xffffffffu, pl, 1);
            pl += __shfl_xor_sync(0xffffffffu, pl, 2);
            pr += __shfl_xor_sync(0xffffffffu, pr, 1);
            pr += __shfl_xor_sync(0xffffffffu, pr, 2);
            if ((lane & 3) == 0) {
                el[row * NH + (lane >> 2)] = pl;
                er[row * NH + (lane >> 2)] = pr;
            }
        }
    }
}

// ---------------- edge softmax + aggregation: one warp per dst node ----------------
__global__ __launch_bounds__(256) void agg_kernel(
    const float* __restrict__ h, const float* __restrict__ el,
    const float* __restrict__ er, float* __restrict__ out, int act) {
    int w = blockIdx.x * 8 + (threadIdx.x >> 5);
    if (w >= NN) return;
    int lane = threadIdx.x & 31;
    int beg = g_off[w], end = g_off[w + 1];

    float4 e0 = ((const float4*)er)[w * 2];
    float4 e1 = ((const float4*)er)[w * 2 + 1];
    float ern[8] = {e0.x, e0.y, e0.z, e0.w, e1.x, e1.y, e1.z, e1.w};

    // phase 1: softmax denominators (lanes strided over edges)
    float z[8];
    #pragma unroll
    for (int t = 0; t < 8; t++) z[t] = 0.f;
    for (int j = beg + lane; j < end; j += 32) {
        int s = g_csr[j];
        float4 l0 = ((const float4*)el)[s * 2];
        float4 l1 = ((const float4*)el)[s * 2 + 1];
        float ev[8] = {l0.x, l0.y, l0.z, l0.w, l1.x, l1.y, l1.z, l1.w};
        #pragma unroll
        for (int t = 0; t < 8; t++) {
            float v = ev[t] + ern[t];
            v = v > 0.f ? v : 0.2f * v;
            z[t] += __expf(v);
        }
    }
    #pragma unroll
    for (int t = 0; t < 8; t++) {
        z[t] += __shfl_xor_sync(0xffffffffu, z[t], 16);
        z[t] += __shfl_xor_sync(0xffffffffu, z[t], 8);
        z[t] += __shfl_xor_sync(0xffffffffu, z[t], 4);
        z[t] += __shfl_xor_sync(0xffffffffu, z[t], 2);
        z[t] += __shfl_xor_sync(0xffffffffu, z[t], 1);
    }

    int head = lane >> 2;  // lane t covers cols 4t..4t+3 -> head t/4
    // select z[head], ern[head] without dynamic-index local-mem spill
    float zh = z[0], erh = ern[0];
    #pragma unroll
    for (int t = 1; t < 8; t++) {
        zh = (head == t) ? z[t] : zh;
        erh = (head == t) ? ern[t] : erh;
    }
    float invz = 1.0f / zh;  // deg==0 -> inf, but never used (empty loop)

    // phase 2: weighted gather-accumulate (lanes split over features).
    // Prefetch CSR indices two ahead to expose more MLP on the h[src] gather.
    float4 acc = make_float4(0.f, 0.f, 0.f, 0.f);
    int s0 = (beg + 0 < end) ? g_csr[beg + 0] : 0;
    int s1 = (beg + 1 < end) ? g_csr[beg + 1] : 0;
    for (int j = beg; j < end; j++) {
        int s = s0;
        s0 = s1;
        s1 = (j + 2 < end) ? g_csr[j + 2] : 0;
        float v = __ldg(&el[s * NH + head]) + erh;
        v = v > 0.f ? v : 0.2f * v;
        float a = __expf(v) * invz;
        float4 hv = ((const float4*)h)[s * 32 + lane];
        acc.x = fmaf(a, hv.x, acc.x);
        acc.y = fmaf(a, hv.y, acc.y);
        acc.z = fmaf(a, hv.z, acc.z);
        acc.w = fmaf(a, hv.w, acc.w);
    }
    if (act) {  // inter-layer leaky_relu(0.01)
        acc.x = acc.x > 0.f ? acc.x : 0.01f * acc.x;
        acc.y = acc.y > 0.f ? acc.y : 0.01f * acc.y;
        acc.z = acc.z > 0.f ? acc.z : 0.01f * acc.z;
        acc.w = acc.w > 0.f ? acc.w : 0.01f * acc.w;
    }
    ((float4*)out)[w * 32 + lane] = acc;
}

// ---------------- launch ----------------
extern "C" void kernel_launch(void* const* d_in, const int* in_sizes, int n_in,
                              void* d_out, int out_size) {
    const float* x   = (const float*)d_in[0];
    const int*   src = (const int*)d_in[1];
    const int*   dst = (const int*)d_in[2];
    const float* W1  = (const float*)d_in[3];
    const float* al1 = (const float*)d_in[4];
    const float* ar1 = (const float*)d_in[5];
    const float* W2  = (const float*)d_in[6];
    const float* al2 = (const float*)d_in[7];
    const float* ar2 = (const float*)d_in[8];
    float* out = (float*)d_out;
    int E = in_sizes[1];

    float *ph, *po, *pel, *per;
    cudaGetSymbolAddress((void**)&ph,  g_h);
    cudaGetSymbolAddress((void**)&po,  g_o);
    cudaGetSymbolAddress((void**)&pel, g_el);
    cudaGetSymbolAddress((void**)&per, g_er);

    // CSR by dst (rebuilt every call; identical inputs -> identical structure)
    zero_cnt_kernel<<<(NN + 255) / 256, 256>>>();
    hist_kernel<<<(E + 255) / 256, 256>>>(dst, E);
    scan_kernel<<<1, 1024>>>();
    scatter_kernel<<<(E + 255) / 256, 256>>>(src, dst, E);

    // layer 1
    gemm_attn<<<(NN + 63) / 64, 256>>>(x, W1, al1, ar1, ph, pel, per);
    agg_kernel<<<NN / 8, 256>>>(ph, pel, per, po, 1);

    // layer 2
    gemm_attn<<<(NN + 63) / 64, 256>>>(po, W2, al2, ar2, ph, pel, per);
    agg_kernel<<<NN / 8, 256>>>(ph, pel, per, out, 0);
}

// round 5
// speedup vs baseline: 1.1634x; 1.1634x over previous
#include <cuda_runtime.h>

#define NN 50000
#define EE 800000
#define DH 128
#define NH 8
#define SCAN_CHUNK 2048
#define NB ((NN + SCAN_CHUNK - 1) / SCAN_CHUNK)   // 25 scan blocks

// ---------------- device scratch (no cudaMalloc allowed) ----------------
__device__ float g_h[NN * DH];     // per-layer projected features h = x@W
__device__ float g_o[NN * DH];     // layer-1 output (activated)
__device__ float g_el[NN * NH];    // attention left logits
__device__ float g_er[NN * NH];    // attention right logits
__device__ int   g_off[NN + 1];    // CSR row offsets (by dst)
__device__ int   g_cur[NN];        // scatter cursors
__device__ int   g_cnt[NN];        // in-degree histogram (zeroed by finalize each call;
                                   // zero-initialized at module load for the first call)
__device__ int   g_csr[EE];        // src node per CSR slot
__device__ int   g_bsum[NB];       // per-scan-block totals
__device__ int   g_bbase[NB + 1];  // exclusive bases per scan block (+ grand total)

// ---------------- CSR build ----------------
__global__ void hist_kernel(const int* __restrict__ dst, int E) {
    int i = blockIdx.x * blockDim.x + threadIdx.x;
    if (i < E) atomicAdd(&g_cnt[dst[i]], 1);
}

// per-block local exclusive scan over 2048 elements, in place into g_cnt.
// 256 threads, 8 elements/thread.
__global__ __launch_bounds__(256) void partial_scan_kernel() {
    __shared__ int ws[8];
    int tid = threadIdx.x, lane = tid & 31, warp = tid >> 5;
    int base = blockIdx.x * SCAN_CHUNK + tid * 8;
    int v[8], s = 0;
    #pragma unroll
    for (int t = 0; t < 8; t++) {
        int i = base + t;
        v[t] = (i < NN) ? g_cnt[i] : 0;
        s += v[t];
    }
    // warp inclusive scan of thread sums
    int x = s;
    #pragma unroll
    for (int o = 1; o < 32; o <<= 1) {
        int y = __shfl_up_sync(0xffffffffu, x, o);
        if (lane >= o) x += y;
    }
    if (lane == 31) ws[warp] = x;
    __syncthreads();
    if (tid == 0) {
        int a = 0;
        #pragma unroll
        for (int w = 0; w < 8; w++) { int t = ws[w]; ws[w] = a; a += t; }
    }
    __syncthreads();
    int excl = ws[warp] + x - s;   // exclusive base for this thread
    #pragma unroll
    for (int t = 0; t < 8; t++) {
        int i = base + t;
        if (i < NN) g_cnt[i] = excl;   // in-place local exclusive offset
        excl += v[t];
    }
    if (tid == 255) g_bsum[blockIdx.x] = ws[7] + x;   // block total
}

// single warp scans the NB (=25) block totals
__global__ void scan_bsum_kernel() {
    int tid = threadIdx.x;                 // 32 threads
    int v = (tid < NB) ? g_bsum[tid] : 0;
    int x = v;
    #pragma unroll
    for (int o = 1; o < 32; o <<= 1) {
        int y = __shfl_up_sync(0xffffffffu, x, o);
        if (tid >= o) x += y;
    }
    if (tid < NB) g_bbase[tid] = x - v;    // exclusive base
    if (tid == 31) g_bbase[NB] = x;        // grand total (== E)
}

// g_off/g_cur = local_excl + block base; re-zero g_cnt for the next call
__global__ void finalize_kernel() {
    int i = blockIdx.x * blockDim.x + threadIdx.x;
    if (i < NN) {
        int off = g_cnt[i] + g_bbase[i / SCAN_CHUNK];
        g_off[i] = off;
        g_cur[i] = off;
        g_cnt[i] = 0;
    }
    if (i == 0) g_off[NN] = g_bbase[NB];
}

__global__ void scatter_kernel(const int* __restrict__ src,
                               const int* __restrict__ dst, int E) {
    int i = blockIdx.x * blockDim.x + threadIdx.x;
    if (i < E) {
        int p = atomicAdd(&g_cur[dst[i]], 1);
        g_csr[p] = src[i];
    }
}

// ---------------- GEMM + attention projections ----------------
// h[r][c] = sum_k x[r][k] * W[k][c];  el[r][hd] = sum_d h[r][hd*16+d]*al[hd][d]
// Block: 256 thr = 8 warps, 64 rows/block (8 rows/warp). Lane t owns cols 4t..4t+3.
// Inner loop processes k in groups of 4 with float4 shared loads:
// 12 LDS.128 per 128 FFMA (vs 36 LDS in the naive version).
__global__ __launch_bounds__(256) void gemm_attn(
    const float* __restrict__ x, const float* __restrict__ W,
    const float* __restrict__ al, const float* __restrict__ ar,
    float* __restrict__ h, float* __restrict__ el, float* __restrict__ er) {
    __shared__ float xs[64 * DH];  // 32 KB
    __shared__ float Ws[32 * DH];  // 16 KB
    int tid = threadIdx.x, lane = tid & 31, warp = tid >> 5;
    int row0 = blockIdx.x * 64;

    for (int idx = tid; idx < 64 * DH / 4; idx += 256) {
        int r = idx >> 5, c4 = idx & 31;
        float4 v = make_float4(0.f, 0.f, 0.f, 0.f);
        if (row0 + r < NN) v = ((const float4*)x)[(row0 + r) * 32 + c4];
        ((float4*)xs)[idx] = v;
    }

    float4 acc[8];
    #pragma unroll
    for (int r = 0; r < 8; r++) acc[r] = make_float4(0.f, 0.f, 0.f, 0.f);

    for (int kc = 0; kc < 4; kc++) {
        __syncthreads();
        for (int idx = tid; idx < 32 * DH / 4; idx += 256)
            ((float4*)Ws)[idx] = ((const float4*)W)[kc * 1024 + idx];
        __syncthreads();
        #pragma unroll
        for (int k4 = 0; k4 < 8; k4++) {          // 4 k-values per iteration
            float4 w0 = ((float4*)Ws)[(k4 * 4 + 0) * 32 + lane];
            float4 w1 = ((float4*)Ws)[(k4 * 4 + 1) * 32 + lane];
            float4 w2 = ((float4*)Ws)[(k4 * 4 + 2) * 32 + lane];
            float4 w3 = ((float4*)Ws)[(k4 * 4 + 3) * 32 + lane];
            #pragma unroll
            for (int r = 0; r < 8; r++) {
                float4 xv = *(const float4*)&xs[(warp * 8 + r) * DH + kc * 32 + k4 * 4];
                acc[r].x = fmaf(xv.x, w0.x, acc[r].x);
                acc[r].y = fmaf(xv.x, w0.y, acc[r].y);
                acc[r].z = fmaf(xv.x, w0.z, acc[r].z);
                acc[r].w = fmaf(xv.x, w0.w, acc[r].w);
                acc[r].x = fmaf(xv.y, w1.x, acc[r].x);
                acc[r].y = fmaf(xv.y, w1.y, acc[r].y);
                acc[r].z = fmaf(xv.y, w1.z, acc[r].z);
                acc[r].w = fmaf(xv.y, w1.w, acc[r].w);
                acc[r].x = fmaf(xv.z, w2.x, acc[r].x);
                acc[r].y = fmaf(xv.z, w2.y, acc[r].y);
                acc[r].z = fmaf(xv.z, w2.z, acc[r].z);
                acc[r].w = fmaf(xv.z, w2.w, acc[r].w);
                acc[r].x = fmaf(xv.w, w3.x, acc[r].x);
                acc[r].y = fmaf(xv.w, w3.y, acc[r].y);
                acc[r].z = fmaf(xv.w, w3.z, acc[r].z);
                acc[r].w = fmaf(xv.w, w3.w, acc[r].w);
            }
        }
    }

    // al/ar flat [H*16]=128 floats; lane t covers exactly al_flat[4t..4t+3]
    float4 alv = ((const float4*)al)[lane];
    float4 arv = ((const float4*)ar)[lane];
    #pragma unroll
    for (int r = 0; r < 8; r++) {
        int row = row0 + warp * 8 + r;
        if (row < NN) {  // uniform per warp
            ((float4*)h)[row * 32 + lane] = acc[r];
            float pl = acc[r].x * alv.x + acc[r].y * alv.y + acc[r].z * alv.z + acc[r].w * alv.w;
            float pr = acc[r].x * arv.x + acc[r].y * arv.y + acc[r].z * arv.z + acc[r].w * arv.w;
            pl += __shfl_xor_sync(0xffffffffu, pl, 1);
            pl += __shfl_xor_sync(0xffffffffu, pl, 2);
            pr += __shfl_xor_sync(0xffffffffu, pr, 1);
            pr += __shfl_xor_sync(0xffffffffu, pr, 2);
            if ((lane & 3) == 0) {
                el[row * NH + (lane >> 2)] = pl;
                er[row * NH + (lane >> 2)] = pr;
            }
        }
    }
}

// ---------------- edge softmax + aggregation: one warp per dst node ----------------
__global__ __launch_bounds__(256) void agg_kernel(
    const float* __restrict__ h, const float* __restrict__ el,
    const float* __restrict__ er, float* __restrict__ out, int act) {
    int w = blockIdx.x * 8 + (threadIdx.x >> 5);
    if (w >= NN) return;
    int lane = threadIdx.x & 31;
    int beg = g_off[w], end = g_off[w + 1];

    float4 e0 = ((const float4*)er)[w * 2];
    float4 e1 = ((const float4*)er)[w * 2 + 1];
    float ern[8] = {e0.x, e0.y, e0.z, e0.w, e1.x, e1.y, e1.z, e1.w};

    // phase 1: softmax denominators (lanes strided over edges)
    float z[8];
    #pragma unroll
    for (int t = 0; t < 8; t++) z[t] = 0.f;
    for (int j = beg + lane; j < end; j += 32) {
        int s = g_csr[j];
        float4 l0 = ((const float4*)el)[s * 2];
        float4 l1 = ((const float4*)el)[s * 2 + 1];
        float ev[8] = {l0.x, l0.y, l0.z, l0.w, l1.x, l1.y, l1.z, l1.w};
        #pragma unroll
        for (int t = 0; t < 8; t++) {
            float v = ev[t] + ern[t];
            v = v > 0.f ? v : 0.2f * v;
            z[t] += __expf(v);
        }
    }
    #pragma unroll
    for (int t = 0; t < 8; t++) {
        z[t] += __shfl_xor_sync(0xffffffffu, z[t], 16);
        z[t] += __shfl_xor_sync(0xffffffffu, z[t], 8);
        z[t] += __shfl_xor_sync(0xffffffffu, z[t], 4);
        z[t] += __shfl_xor_sync(0xffffffffu, z[t], 2);
        z[t] += __shfl_xor_sync(0xffffffffu, z[t], 1);
    }

    int head = lane >> 2;  // lane t covers cols 4t..4t+3 -> head t/4
    // select z[head], ern[head] without dynamic-index local-mem spill
    float zh = z[0], erh = ern[0];
    #pragma unroll
    for (int t = 1; t < 8; t++) {
        zh = (head == t) ? z[t] : zh;
        erh = (head == t) ? ern[t] : erh;
    }
    float invz = 1.0f / zh;  // deg==0 -> inf, but never used (empty loop)

    // phase 2: weighted gather-accumulate (lanes split over features).
    // Prefetch CSR indices two ahead to expose more MLP on the h[src] gather.
    float4 acc = make_float4(0.f, 0.f, 0.f, 0.f);
    int s0 = (beg + 0 < end) ? g_csr[beg + 0] : 0;
    int s1 = (beg + 1 < end) ? g_csr[beg + 1] : 0;
    for (int j = beg; j < end; j++) {
        int s = s0;
        s0 = s1;
        s1 = (j + 2 < end) ? g_csr[j + 2] : 0;
        float v = __ldg(&el[s * NH + head]) + erh;
        v = v > 0.f ? v : 0.2f * v;
        float a = __expf(v) * invz;
        float4 hv = ((const float4*)h)[s * 32 + lane];
        acc.x = fmaf(a, hv.x, acc.x);
        acc.y = fmaf(a, hv.y, acc.y);
        acc.z = fmaf(a, hv.z, acc.z);
        acc.w = fmaf(a, hv.w, acc.w);
    }
    if (act) {  // inter-layer leaky_relu(0.01)
        acc.x = acc.x > 0.f ? acc.x : 0.01f * acc.x;
        acc.y = acc.y > 0.f ? acc.y : 0.01f * acc.y;
        acc.z = acc.z > 0.f ? acc.z : 0.01f * acc.z;
        acc.w = acc.w > 0.f ? acc.w : 0.01f * acc.w;
    }
    ((float4*)out)[w * 32 + lane] = acc;
}

// ---------------- launch ----------------
extern "C" void kernel_launch(void* const* d_in, const int* in_sizes, int n_in,
                              void* d_out, int out_size) {
    const float* x   = (const float*)d_in[0];
    const int*   src = (const int*)d_in[1];
    const int*   dst = (const int*)d_in[2];
    const float* W1  = (const float*)d_in[3];
    const float* al1 = (const float*)d_in[4];
    const float* ar1 = (const float*)d_in[5];
    const float* W2  = (const float*)d_in[6];
    const float* al2 = (const float*)d_in[7];
    const float* ar2 = (const float*)d_in[8];
    float* out = (float*)d_out;
    int E = in_sizes[1];

    float *ph, *po, *pel, *per;
    cudaGetSymbolAddress((void**)&ph,  g_h);
    cudaGetSymbolAddress((void**)&po,  g_o);
    cudaGetSymbolAddress((void**)&pel, g_el);
    cudaGetSymbolAddress((void**)&per, g_er);

    // CSR by dst. g_cnt starts zero (module-load zero-init on call 1;
    // finalize_kernel re-zeroes it each call after its last read).
    hist_kernel<<<(E + 255) / 256, 256>>>(dst, E);          // launch 0
    partial_scan_kernel<<<NB, 256>>>();                     // launch 1
    scan_bsum_kernel<<<1, 32>>>();                          // launch 2
    finalize_kernel<<<(NN + 255) / 256, 256>>>();           // launch 3
    scatter_kernel<<<(E + 255) / 256, 256>>>(src, dst, E);  // launch 4

    // layer 1
    gemm_attn<<<(NN + 63) / 64, 256>>>(x, W1, al1, ar1, ph, pel, per);  // launch 5 (ncu)
    agg_kernel<<<NN / 8, 256>>>(ph, pel, per, po, 1);

    // layer 2
    gemm_attn<<<(NN + 63) / 64, 256>>>(po, W2, al2, ar2, ph, pel, per);
    agg_kernel<<<NN / 8, 256>>>(ph, pel, per, out, 0);
}

// round 6
// speedup vs baseline: 1.2611x; 1.0839x over previous
#include <cuda_runtime.h>

#define NN 50000
#define EE 800000
#define DH 128
#define NH 8
#define SCAN_CHUNK 2048
#define NB ((NN + SCAN_CHUNK - 1) / SCAN_CHUNK)   // 25 scan blocks

// ---------------- device scratch (no cudaMalloc allowed) ----------------
__device__ float g_h[NN * DH];     // per-layer projected features h = x@W
__device__ float g_o[NN * DH];     // layer-1 output (activated)
__device__ float g_el[NN * NH];    // attention left logits
__device__ float g_er[NN * NH];    // attention right logits
__device__ int   g_off[NN + 1];    // CSR row offsets (by dst)
__device__ int   g_cur[NN];        // scatter cursors
__device__ int   g_cnt[NN];        // in-degree histogram (zeroed by finalize each call;
                                   // zero-initialized at module load for the first call)
__device__ int   g_csr[EE];        // src node per CSR slot
__device__ int   g_bsum[NB];       // per-scan-block totals
__device__ int   g_bbase[NB + 1];  // exclusive bases per scan block (+ grand total)

// ---------------- CSR build ----------------
__global__ void hist_kernel(const int* __restrict__ dst, int E) {
    int i = blockIdx.x * blockDim.x + threadIdx.x;
    if (i < E) atomicAdd(&g_cnt[dst[i]], 1);
}

// per-block local exclusive scan over 2048 elements, in place into g_cnt.
// 256 threads, 8 elements/thread.
__global__ __launch_bounds__(256) void partial_scan_kernel() {
    __shared__ int ws[8];
    int tid = threadIdx.x, lane = tid & 31, warp = tid >> 5;
    int base = blockIdx.x * SCAN_CHUNK + tid * 8;
    int v[8], s = 0;
    #pragma unroll
    for (int t = 0; t < 8; t++) {
        int i = base + t;
        v[t] = (i < NN) ? g_cnt[i] : 0;
        s += v[t];
    }
    // warp inclusive scan of thread sums
    int x = s;
    #pragma unroll
    for (int o = 1; o < 32; o <<= 1) {
        int y = __shfl_up_sync(0xffffffffu, x, o);
        if (lane >= o) x += y;
    }
    if (lane == 31) ws[warp] = x;
    __syncthreads();
    if (tid == 0) {
        int a = 0;
        #pragma unroll
        for (int w = 0; w < 8; w++) { int t = ws[w]; ws[w] = a; a += t; }
    }
    __syncthreads();
    int excl = ws[warp] + x - s;   // exclusive base for this thread
    #pragma unroll
    for (int t = 0; t < 8; t++) {
        int i = base + t;
        if (i < NN) g_cnt[i] = excl;   // in-place local exclusive offset
        excl += v[t];
    }
    if (tid == 255) g_bsum[blockIdx.x] = ws[7] + x;   // block total
}

// single warp scans the NB (=25) block totals
__global__ void scan_bsum_kernel() {
    int tid = threadIdx.x;                 // 32 threads
    int v = (tid < NB) ? g_bsum[tid] : 0;
    int x = v;
    #pragma unroll
    for (int o = 1; o < 32; o <<= 1) {
        int y = __shfl_up_sync(0xffffffffu, x, o);
        if (tid >= o) x += y;
    }
    if (tid < NB) g_bbase[tid] = x - v;    // exclusive base
    if (tid == 31) g_bbase[NB] = x;        // grand total (== E)
}

// g_off/g_cur = local_excl + block base; re-zero g_cnt for the next call
__global__ void finalize_kernel() {
    int i = blockIdx.x * blockDim.x + threadIdx.x;
    if (i < NN) {
        int off = g_cnt[i] + g_bbase[i / SCAN_CHUNK];
        g_off[i] = off;
        g_cur[i] = off;
        g_cnt[i] = 0;
    }
    if (i == 0) g_off[NN] = g_bbase[NB];
}

__global__ void scatter_kernel(const int* __restrict__ src,
                               const int* __restrict__ dst, int E) {
    int i = blockIdx.x * blockDim.x + threadIdx.x;
    if (i < E) {
        int p = atomicAdd(&g_cur[dst[i]], 1);
        g_csr[p] = src[i];
    }
}

// ---------------- GEMM + attention projections ----------------
// h[r][c] = sum_k x[r][k] * W[k][c];  el[r][hd] = sum_d h[r][hd*16+d]*al[hd][d]
// Block: 256 thr = 8 warps, 64 rows/block (8 rows/warp). Lane t owns cols 4t..4t+3.
// Inner loop processes k in groups of 4 with float4 shared loads:
// 12 LDS.128 per 128 FFMA.
__global__ __launch_bounds__(256) void gemm_attn(
    const float* __restrict__ x, const float* __restrict__ W,
    const float* __restrict__ al, const float* __restrict__ ar,
    float* __restrict__ h, float* __restrict__ el, float* __restrict__ er) {
    __shared__ float xs[64 * DH];  // 32 KB
    __shared__ float Ws[32 * DH];  // 16 KB
    int tid = threadIdx.x, lane = tid & 31, warp = tid >> 5;
    int row0 = blockIdx.x * 64;

    for (int idx = tid; idx < 64 * DH / 4; idx += 256) {
        int r = idx >> 5, c4 = idx & 31;
        float4 v = make_float4(0.f, 0.f, 0.f, 0.f);
        if (row0 + r < NN) v = ((const float4*)x)[(row0 + r) * 32 + c4];
        ((float4*)xs)[idx] = v;
    }

    float4 acc[8];
    #pragma unroll
    for (int r = 0; r < 8; r++) acc[r] = make_float4(0.f, 0.f, 0.f, 0.f);

    for (int kc = 0; kc < 4; kc++) {
        __syncthreads();
        for (int idx = tid; idx < 32 * DH / 4; idx += 256)
            ((float4*)Ws)[idx] = ((const float4*)W)[kc * 1024 + idx];
        __syncthreads();
        #pragma unroll
        for (int k4 = 0; k4 < 8; k4++) {          // 4 k-values per iteration
            float4 w0 = ((float4*)Ws)[(k4 * 4 + 0) * 32 + lane];
            float4 w1 = ((float4*)Ws)[(k4 * 4 + 1) * 32 + lane];
            float4 w2 = ((float4*)Ws)[(k4 * 4 + 2) * 32 + lane];
            float4 w3 = ((float4*)Ws)[(k4 * 4 + 3) * 32 + lane];
            #pragma unroll
            for (int r = 0; r < 8; r++) {
                float4 xv = *(const float4*)&xs[(warp * 8 + r) * DH + kc * 32 + k4 * 4];
                acc[r].x = fmaf(xv.x, w0.x, acc[r].x);
                acc[r].y = fmaf(xv.x, w0.y, acc[r].y);
                acc[r].z = fmaf(xv.x, w0.z, acc[r].z);
                acc[r].w = fmaf(xv.x, w0.w, acc[r].w);
                acc[r].x = fmaf(xv.y, w1.x, acc[r].x);
                acc[r].y = fmaf(xv.y, w1.y, acc[r].y);
                acc[r].z = fmaf(xv.y, w1.z, acc[r].z);
                acc[r].w = fmaf(xv.y, w1.w, acc[r].w);
                acc[r].x = fmaf(xv.z, w2.x, acc[r].x);
                acc[r].y = fmaf(xv.z, w2.y, acc[r].y);
                acc[r].z = fmaf(xv.z, w2.z, acc[r].z);
                acc[r].w = fmaf(xv.z, w2.w, acc[r].w);
                acc[r].x = fmaf(xv.w, w3.x, acc[r].x);
                acc[r].y = fmaf(xv.w, w3.y, acc[r].y);
                acc[r].z = fmaf(xv.w, w3.z, acc[r].z);
                acc[r].w = fmaf(xv.w, w3.w, acc[r].w);
            }
        }
    }

    // al/ar flat [H*16]=128 floats; lane t covers exactly al_flat[4t..4t+3]
    float4 alv = ((const float4*)al)[lane];
    float4 arv = ((const float4*)ar)[lane];
    #pragma unroll
    for (int r = 0; r < 8; r++) {
        int row = row0 + warp * 8 + r;
        if (row < NN) {  // uniform per warp
            ((float4*)h)[row * 32 + lane] = acc[r];
            float pl = acc[r].x * alv.x + acc[r].y * alv.y + acc[r].z * alv.z + acc[r].w * alv.w;
            float pr = acc[r].x * arv.x + acc[r].y * arv.y + acc[r].z * arv.z + acc[r].w * arv.w;
            pl += __shfl_xor_sync(0xffffffffu, pl, 1);
            pl += __shfl_xor_sync(0xffffffffu, pl, 2);
            pr += __shfl_xor_sync(0xffffffffu, pr, 1);
            pr += __shfl_xor_sync(0xffffffffu, pr, 2);
            if ((lane & 3) == 0) {
                el[row * NH + (lane >> 2)] = pl;
                er[row * NH + (lane >> 2)] = pr;
            }
        }
    }
}

// ---------------- fused edge softmax + aggregation: one warp per dst node ----------------
// Single edge pass: out = (sum_e ex_e * h[src_e]) / (sum_e ex_e), per head.
// No max-subtraction needed (logits O(1)); normalization folded into a final divide.
// Lane t owns feature cols 4t..4t+3 -> head t/4; each lane tracks its head's z.
__global__ __launch_bounds__(256) void agg_kernel(
    const float* __restrict__ h, const float* __restrict__ el,
    const float* __restrict__ er, float* __restrict__ out, int act) {
    int w = blockIdx.x * 8 + (threadIdx.x >> 5);
    if (w >= NN) return;
    int lane = threadIdx.x & 31;
    int head = lane >> 2;
    int beg = g_off[w], end = g_off[w + 1];

    float erh = __ldg(&er[w * NH + head]);

    float4 accA = make_float4(0.f, 0.f, 0.f, 0.f);
    float4 accB = make_float4(0.f, 0.f, 0.f, 0.f);
    float zA = 0.f, zB = 0.f;

    int j = beg;
    for (; j + 1 < end; j += 2) {
        int sA = g_csr[j];
        int sB = g_csr[j + 1];
        float vA = __ldg(&el[sA * NH + head]) + erh;
        float vB = __ldg(&el[sB * NH + head]) + erh;
        vA = vA > 0.f ? vA : 0.2f * vA;
        vB = vB > 0.f ? vB : 0.2f * vB;
        float aA = __expf(vA);
        float aB = __expf(vB);
        float4 hA = ((const float4*)h)[sA * 32 + lane];
        float4 hB = ((const float4*)h)[sB * 32 + lane];
        zA += aA;
        zB += aB;
        accA.x = fmaf(aA, hA.x, accA.x);
        accA.y = fmaf(aA, hA.y, accA.y);
        accA.z = fmaf(aA, hA.z, accA.z);
        accA.w = fmaf(aA, hA.w, accA.w);
        accB.x = fmaf(aB, hB.x, accB.x);
        accB.y = fmaf(aB, hB.y, accB.y);
        accB.z = fmaf(aB, hB.z, accB.z);
        accB.w = fmaf(aB, hB.w, accB.w);
    }
    if (j < end) {
        int s = g_csr[j];
        float v = __ldg(&el[s * NH + head]) + erh;
        v = v > 0.f ? v : 0.2f * v;
        float a = __expf(v);
        float4 hv = ((const float4*)h)[s * 32 + lane];
        zA += a;
        accA.x = fmaf(a, hv.x, accA.x);
        accA.y = fmaf(a, hv.y, accA.y);
        accA.z = fmaf(a, hv.z, accA.z);
        accA.w = fmaf(a, hv.w, accA.w);
    }

    float z = zA + zB;
    float4 acc = make_float4(accA.x + accB.x, accA.y + accB.y,
                             accA.z + accB.z, accA.w + accB.w);
    float invz = (end > beg) ? 1.0f / z : 0.f;   // deg-0 -> output 0 (matches ref)
    acc.x *= invz; acc.y *= invz; acc.z *= invz; acc.w *= invz;

    if (act) {  // inter-layer leaky_relu(0.01)
        acc.x = acc.x > 0.f ? acc.x : 0.01f * acc.x;
        acc.y = acc.y > 0.f ? acc.y : 0.01f * acc.y;
        acc.z = acc.z > 0.f ? acc.z : 0.01f * acc.z;
        acc.w = acc.w > 0.f ? acc.w : 0.01f * acc.w;
    }
    ((float4*)out)[w * 32 + lane] = acc;
}

// ---------------- launch ----------------
extern "C" void kernel_launch(void* const* d_in, const int* in_sizes, int n_in,
                              void* d_out, int out_size) {
    const float* x   = (const float*)d_in[0];
    const int*   src = (const int*)d_in[1];
    const int*   dst = (const int*)d_in[2];
    const float* W1  = (const float*)d_in[3];
    const float* al1 = (const float*)d_in[4];
    const float* ar1 = (const float*)d_in[5];
    const float* W2  = (const float*)d_in[6];
    const float* al2 = (const float*)d_in[7];
    const float* ar2 = (const float*)d_in[8];
    float* out = (float*)d_out;
    int E = in_sizes[1];

    float *ph, *po, *pel, *per;
    cudaGetSymbolAddress((void**)&ph,  g_h);
    cudaGetSymbolAddress((void**)&po,  g_o);
    cudaGetSymbolAddress((void**)&pel, g_el);
    cudaGetSymbolAddress((void**)&per, g_er);

    // CSR by dst. g_cnt starts zero (module-load zero-init on call 1;
    // finalize_kernel re-zeroes it each call after its last read).
    // gemm1 placed at launch index 3 so ncu (-s 5, two harness launches ahead)
    // captures it this round. gemm1 is independent of the CSR pipeline.
    hist_kernel<<<(E + 255) / 256, 256>>>(dst, E);                      // 0
    partial_scan_kernel<<<NB, 256>>>();                                 // 1
    scan_bsum_kernel<<<1, 32>>>();                                      // 2
    gemm_attn<<<(NN + 63) / 64, 256>>>(x, W1, al1, ar1, ph, pel, per);  // 3 (ncu)
    finalize_kernel<<<(NN + 255) / 256, 256>>>();                       // 4
    scatter_kernel<<<(E + 255) / 256, 256>>>(src, dst, E);              // 5
    agg_kernel<<<NN / 8, 256>>>(ph, pel, per, po, 1);                   // 6

    // layer 2
    gemm_attn<<<(NN + 63) / 64, 256>>>(po, W2, al2, ar2, ph, pel, per); // 7
    agg_kernel<<<NN / 8, 256>>>(ph, pel, per, out, 0);                  // 8
}

// round 7
// speedup vs baseline: 1.3088x; 1.0379x over previous
#include <cuda_runtime.h>

#define NN 50000
#define EE 800000
#define DH 128
#define NH 8
#define SCAN_CHUNK 2048
#define NB ((NN + SCAN_CHUNK - 1) / SCAN_CHUNK)   // 25 scan blocks

// ---------------- device scratch (no cudaMalloc allowed) ----------------
__device__ float g_h[NN * DH];     // per-layer projected features h = x@W
__device__ float g_o[NN * DH];     // layer-1 output (activated)
__device__ float g_el[NN * NH];    // attention left logits
__device__ float g_er[NN * NH];    // attention right logits
__device__ int   g_off[NN + 1];    // CSR row offsets (by dst)
__device__ int   g_cur[NN];        // scatter cursors
__device__ int   g_cnt[NN];        // in-degree histogram (zeroed by finalize each call;
                                   // zero-initialized at module load for the first call)
__device__ int   g_csr[EE];        // src node per CSR slot
__device__ int   g_bsum[NB];       // per-scan-block totals
__device__ int   g_bbase[NB + 1];  // exclusive bases per scan block (+ grand total)

// ---------------- f32x2 helpers ----------------
__device__ __forceinline__ unsigned long long pack_dup(float v) {
    unsigned long long r;
    asm("mov.b64 %0, {%1, %1};" : "=l"(r) : "r"(__float_as_uint(v)));
    return r;
}
__device__ __forceinline__ void fma2(unsigned long long& d,
                                     unsigned long long a, unsigned long long b) {
    asm("fma.rn.f32x2 %0, %1, %2, %0;" : "+l"(d) : "l"(a), "l"(b));
}
__device__ __forceinline__ float2 unpack2(unsigned long long v) {
    float2 f;
    asm("mov.b64 {%0, %1}, %2;" : "=f"(f.x), "=f"(f.y) : "l"(v));
    return f;
}

// ---------------- CSR build ----------------
__global__ void hist_kernel(const int* __restrict__ dst, int E) {
    int i = blockIdx.x * blockDim.x + threadIdx.x;
    if (i < E) atomicAdd(&g_cnt[dst[i]], 1);
}

// per-block local exclusive scan over 2048 elements, in place into g_cnt.
// 256 threads, 8 elements/thread.
__global__ __launch_bounds__(256) void partial_scan_kernel() {
    __shared__ int ws[8];
    int tid = threadIdx.x, lane = tid & 31, warp = tid >> 5;
    int base = blockIdx.x * SCAN_CHUNK + tid * 8;
    int v[8], s = 0;
    #pragma unroll
    for (int t = 0; t < 8; t++) {
        int i = base + t;
        v[t] = (i < NN) ? g_cnt[i] : 0;
        s += v[t];
    }
    // warp inclusive scan of thread sums
    int x = s;
    #pragma unroll
    for (int o = 1; o < 32; o <<= 1) {
        int y = __shfl_up_sync(0xffffffffu, x, o);
        if (lane >= o) x += y;
    }
    if (lane == 31) ws[warp] = x;
    __syncthreads();
    if (tid == 0) {
        int a = 0;
        #pragma unroll
        for (int w = 0; w < 8; w++) { int t = ws[w]; ws[w] = a; a += t; }
    }
    __syncthreads();
    int excl = ws[warp] + x - s;   // exclusive base for this thread
    #pragma unroll
    for (int t = 0; t < 8; t++) {
        int i = base + t;
        if (i < NN) g_cnt[i] = excl;   // in-place local exclusive offset
        excl += v[t];
    }
    if (tid == 255) g_bsum[blockIdx.x] = ws[7] + x;   // block total
}

// single warp scans the NB (=25) block totals
__global__ void scan_bsum_kernel() {
    int tid = threadIdx.x;                 // 32 threads
    int v = (tid < NB) ? g_bsum[tid] : 0;
    int x = v;
    #pragma unroll
    for (int o = 1; o < 32; o <<= 1) {
        int y = __shfl_up_sync(0xffffffffu, x, o);
        if (tid >= o) x += y;
    }
    if (tid < NB) g_bbase[tid] = x - v;    // exclusive base
    if (tid == 31) g_bbase[NB] = x;        // grand total (== E)
}

// g_off/g_cur = local_excl + block base; re-zero g_cnt for the next call
__global__ void finalize_kernel() {
    int i = blockIdx.x * blockDim.x + threadIdx.x;
    if (i < NN) {
        int off = g_cnt[i] + g_bbase[i / SCAN_CHUNK];
        g_off[i] = off;
        g_cur[i] = off;
        g_cnt[i] = 0;
    }
    if (i == 0) g_off[NN] = g_bbase[NB];
}

__global__ void scatter_kernel(const int* __restrict__ src,
                               const int* __restrict__ dst, int E) {
    int i = blockIdx.x * blockDim.x + threadIdx.x;
    if (i < E) {
        int p = atomicAdd(&g_cur[dst[i]], 1);
        g_csr[p] = src[i];
    }
}

// ---------------- GEMM + attention projections (packed f32x2 FMA) ----------------
// h[r][c] = sum_k x[r][k] * W[k][c];  el[r][hd] = sum_d h[r][hd*16+d]*al[hd][d]
// Block: 256 thr = 8 warps, 64 rows/block (8 rows/warp). Lane t owns cols 4t..4t+3,
// held as two f32x2 accumulators. W pairs loaded as ulonglong2; x broadcast packed
// via mov.b64 {r,r}. fma.rn.f32x2 = 2 IEEE fp32 FMAs/inst -> halves fma-pipe load.
__global__ __launch_bounds__(256) void gemm_attn(
    const float* __restrict__ x, const float* __restrict__ W,
    const float* __restrict__ al, const float* __restrict__ ar,
    float* __restrict__ h, float* __restrict__ el, float* __restrict__ er) {
    __shared__ float xs[64 * DH];  // 32 KB
    __shared__ float Ws[32 * DH];  // 16 KB
    int tid = threadIdx.x, lane = tid & 31, warp = tid >> 5;
    int row0 = blockIdx.x * 64;

    for (int idx = tid; idx < 64 * DH / 4; idx += 256) {
        int r = idx >> 5, c4 = idx & 31;
        float4 v = make_float4(0.f, 0.f, 0.f, 0.f);
        if (row0 + r < NN) v = ((const float4*)x)[(row0 + r) * 32 + c4];
        ((float4*)xs)[idx] = v;
    }

    unsigned long long acc[8][2];
    #pragma unroll
    for (int r = 0; r < 8; r++) { acc[r][0] = 0ull; acc[r][1] = 0ull; }

    for (int kc = 0; kc < 4; kc++) {
        __syncthreads();
        for (int idx = tid; idx < 32 * DH / 4; idx += 256)
            ((float4*)Ws)[idx] = ((const float4*)W)[kc * 1024 + idx];
        __syncthreads();
        #pragma unroll
        for (int k4 = 0; k4 < 8; k4++) {          // 4 k-values per iteration
            ulonglong2 w0 = ((const ulonglong2*)Ws)[(k4 * 4 + 0) * 32 + lane];
            ulonglong2 w1 = ((const ulonglong2*)Ws)[(k4 * 4 + 1) * 32 + lane];
            ulonglong2 w2 = ((const ulonglong2*)Ws)[(k4 * 4 + 2) * 32 + lane];
            ulonglong2 w3 = ((const ulonglong2*)Ws)[(k4 * 4 + 3) * 32 + lane];
            #pragma unroll
            for (int r = 0; r < 8; r++) {
                float4 xv = *(const float4*)&xs[(warp * 8 + r) * DH + kc * 32 + k4 * 4];
                unsigned long long xx;
                xx = pack_dup(xv.x);
                fma2(acc[r][0], xx, w0.x);
                fma2(acc[r][1], xx, w0.y);
                xx = pack_dup(xv.y);
                fma2(acc[r][0], xx, w1.x);
                fma2(acc[r][1], xx, w1.y);
                xx = pack_dup(xv.z);
                fma2(acc[r][0], xx, w2.x);
                fma2(acc[r][1], xx, w2.y);
                xx = pack_dup(xv.w);
                fma2(acc[r][0], xx, w3.x);
                fma2(acc[r][1], xx, w3.y);
            }
        }
    }

    // al/ar flat [H*16]=128 floats; lane t covers exactly al_flat[4t..4t+3]
    float4 alv = ((const float4*)al)[lane];
    float4 arv = ((const float4*)ar)[lane];
    #pragma unroll
    for (int r = 0; r < 8; r++) {
        int row = row0 + warp * 8 + r;
        if (row < NN) {  // uniform per warp
            float2 p0 = unpack2(acc[r][0]);
            float2 p1 = unpack2(acc[r][1]);
            float4 a4 = make_float4(p0.x, p0.y, p1.x, p1.y);
            ((float4*)h)[row * 32 + lane] = a4;
            float pl = a4.x * alv.x + a4.y * alv.y + a4.z * alv.z + a4.w * alv.w;
            float pr = a4.x * arv.x + a4.y * arv.y + a4.z * arv.z + a4.w * arv.w;
            pl += __shfl_xor_sync(0xffffffffu, pl, 1);
            pl += __shfl_xor_sync(0xffffffffu, pl, 2);
            pr += __shfl_xor_sync(0xffffffffu, pr, 1);
            pr += __shfl_xor_sync(0xffffffffu, pr, 2);
            if ((lane & 3) == 0) {
                el[row * NH + (lane >> 2)] = pl;
                er[row * NH + (lane >> 2)] = pr;
            }
        }
    }
}

// ---------------- fused edge softmax + aggregation: one warp per dst node ----------------
// Single edge pass: out = (sum_e ex_e * h[src_e]) / (sum_e ex_e), per head.
// No max-subtraction needed (logits O(1)); normalization folded into a final divide.
// Lane t owns feature cols 4t..4t+3 -> head t/4; each lane tracks its head's z.
__global__ __launch_bounds__(256) void agg_kernel(
    const float* __restrict__ h, const float* __restrict__ el,
    const float* __restrict__ er, float* __restrict__ out, int act) {
    int w = blockIdx.x * 8 + (threadIdx.x >> 5);
    if (w >= NN) return;
    int lane = threadIdx.x & 31;
    int head = lane >> 2;
    int beg = g_off[w], end = g_off[w + 1];

    float erh = __ldg(&er[w * NH + head]);

    float4 accA = make_float4(0.f, 0.f, 0.f, 0.f);
    float4 accB = make_float4(0.f, 0.f, 0.f, 0.f);
    float zA = 0.f, zB = 0.f;

    int j = beg;
    for (; j + 1 < end; j += 2) {
        int sA = g_csr[j];
        int sB = g_csr[j + 1];
        float vA = __ldg(&el[sA * NH + head]) + erh;
        float vB = __ldg(&el[sB * NH + head]) + erh;
        vA = vA > 0.f ? vA : 0.2f * vA;
        vB = vB > 0.f ? vB : 0.2f * vB;
        float aA = __expf(vA);
        float aB = __expf(vB);
        float4 hA = ((const float4*)h)[sA * 32 + lane];
        float4 hB = ((const float4*)h)[sB * 32 + lane];
        zA += aA;
        zB += aB;
        accA.x = fmaf(aA, hA.x, accA.x);
        accA.y = fmaf(aA, hA.y, accA.y);
        accA.z = fmaf(aA, hA.z, accA.z);
        accA.w = fmaf(aA, hA.w, accA.w);
        accB.x = fmaf(aB, hB.x, accB.x);
        accB.y = fmaf(aB, hB.y, accB.y);
        accB.z = fmaf(aB, hB.z, accB.z);
        accB.w = fmaf(aB, hB.w, accB.w);
    }
    if (j < end) {
        int s = g_csr[j];
        float v = __ldg(&el[s * NH + head]) + erh;
        v = v > 0.f ? v : 0.2f * v;
        float a = __expf(v);
        float4 hv = ((const float4*)h)[s * 32 + lane];
        zA += a;
        accA.x = fmaf(a, hv.x, accA.x);
        accA.y = fmaf(a, hv.y, accA.y);
        accA.z = fmaf(a, hv.z, accA.z);
        accA.w = fmaf(a, hv.w, accA.w);
    }

    float z = zA + zB;
    float4 acc = make_float4(accA.x + accB.x, accA.y + accB.y,
                             accA.z + accB.z, accA.w + accB.w);
    float invz = (end > beg) ? 1.0f / z : 0.f;   // deg-0 -> output 0 (matches ref)
    acc.x *= invz; acc.y *= invz; acc.z *= invz; acc.w *= invz;

    if (act) {  // inter-layer leaky_relu(0.01)
        acc.x = acc.x > 0.f ? acc.x : 0.01f * acc.x;
        acc.y = acc.y > 0.f ? acc.y : 0.01f * acc.y;
        acc.z = acc.z > 0.f ? acc.z : 0.01f * acc.z;
        acc.w = acc.w > 0.f ? acc.w : 0.01f * acc.w;
    }
    ((float4*)out)[w * 32 + lane] = acc;
}

// ---------------- launch ----------------
extern "C" void kernel_launch(void* const* d_in, const int* in_sizes, int n_in,
                              void* d_out, int out_size) {
    const float* x   = (const float*)d_in[0];
    const int*   src = (const int*)d_in[1];
    const int*   dst = (const int*)d_in[2];
    const float* W1  = (const float*)d_in[3];
    const float* al1 = (const float*)d_in[4];
    const float* ar1 = (const float*)d_in[5];
    const float* W2  = (const float*)d_in[6];
    const float* al2 = (const float*)d_in[7];
    const float* ar2 = (const float*)d_in[8];
    float* out = (float*)d_out;
    int E = in_sizes[1];

    float *ph, *po, *pel, *per;
    cudaGetSymbolAddress((void**)&ph,  g_h);
    cudaGetSymbolAddress((void**)&po,  g_o);
    cudaGetSymbolAddress((void**)&pel, g_el);
    cudaGetSymbolAddress((void**)&per, g_er);

    // CSR by dst. g_cnt starts zero (module-load zero-init on call 1;
    // finalize_kernel re-zeroes it each call after its last read).
    // gemm1 stays at launch index 3 so ncu (-s 5, two harness launches ahead)
    // captures the reworked GEMM this round. gemm1 is CSR-independent.
    hist_kernel<<<(E + 255) / 256, 256>>>(dst, E);                      // 0
    partial_scan_kernel<<<NB, 256>>>();                                 // 1
    scan_bsum_kernel<<<1, 32>>>();                                      // 2
    gemm_attn<<<(NN + 63) / 64, 256>>>(x, W1, al1, ar1, ph, pel, per);  // 3 (ncu)
    finalize_kernel<<<(NN + 255) / 256, 256>>>();                       // 4
    scatter_kernel<<<(E + 255) / 256, 256>>>(src, dst, E);              // 5
    agg_kernel<<<NN / 8, 256>>>(ph, pel, per, po, 1);                   // 6

    // layer 2
    gemm_attn<<<(NN + 63) / 64, 256>>>(po, W2, al2, ar2, ph, pel, per); // 7
    agg_kernel<<<NN / 8, 256>>>(ph, pel, per, out, 0);                  // 8
}

// round 8
// speedup vs baseline: 1.3890x; 1.0612x over previous
#include <cuda_runtime.h>
#include <stdint.h>

#define NN 50000
#define EE 800000
#define DH 128
#define NH 8
#define SCAN_CHUNK 2048
#define NB ((NN + SCAN_CHUNK - 1) / SCAN_CHUNK)   // 25 scan blocks

// ---------------- device scratch (no cudaMalloc allowed) ----------------
__device__ float    g_h[NN * DH];     // per-layer projected features h = x@W
__device__ float    g_o[NN * DH];     // layer-1 output (activated)
__device__ float    g_el[NN * NH];    // attention left logits
__device__ float    g_er[NN * NH];    // attention right logits
__device__ int      g_off[NN + 1];    // CSR row offsets (by dst)
__device__ int      g_cur[NN];        // scatter cursors
__device__ int      g_cnt[NN];        // in-degree histogram
__device__ int      g_csr[EE];        // src node per CSR slot
__device__ int      g_bsum[NB];
__device__ int      g_bbase[NB + 1];
__device__ uint32_t g_wt_hi[128 * 128];  // W split, chunk-major [kc][c][kk]
__device__ uint32_t g_wt_lo[128 * 128];

// ---------------- tf32 helpers ----------------
__device__ __forceinline__ uint32_t f2tf32(float f) {
    uint32_t r;
    asm("cvt.rna.tf32.f32 %0, %1;" : "=r"(r) : "f"(f));
    return r;
}
// D += A(16x8,row) * B(8x8,col), tf32 inputs, f32 accum
__device__ __forceinline__ void mma_tf32(float* c, const uint32_t* a,
                                         uint32_t b0, uint32_t b1) {
    asm("mma.sync.aligned.m16n8k8.row.col.f32.tf32.tf32.f32 "
        "{%0,%1,%2,%3}, {%4,%5,%6,%7}, {%8,%9}, {%0,%1,%2,%3};"
        : "+f"(c[0]), "+f"(c[1]), "+f"(c[2]), "+f"(c[3])
        : "r"(a[0]), "r"(a[1]), "r"(a[2]), "r"(a[3]), "r"(b0), "r"(b1));
}

// ---------------- W pre-split: fp32 -> tf32 hi/lo, chunk-major ----------------
// In: W[k][c] row-major 128x128. Out layout: [(k/16)][c][k%16] (2048 words/chunk).
__global__ void w_split_kernel(const float* __restrict__ W,
                               uint32_t* __restrict__ hi, uint32_t* __restrict__ lo) {
    int i = blockIdx.x * 256 + threadIdx.x;   // 16384 elements
    int k = i >> 7, c = i & 127;
    float v = W[i];
    uint32_t hb = f2tf32(v);
    float lres = v - __uint_as_float(hb);
    int o = (k >> 4) * 2048 + c * 16 + (k & 15);
    hi[o] = hb;
    lo[o] = f2tf32(lres);
}

// ---------------- CSR build ----------------
__global__ void hist_kernel(const int* __restrict__ dst, int E) {
    int i = blockIdx.x * blockDim.x + threadIdx.x;
    if (i < E) atomicAdd(&g_cnt[dst[i]], 1);
}

__global__ __launch_bounds__(256) void partial_scan_kernel() {
    __shared__ int ws[8];
    int tid = threadIdx.x, lane = tid & 31, warp = tid >> 5;
    int base = blockIdx.x * SCAN_CHUNK + tid * 8;
    int v[8], s = 0;
    #pragma unroll
    for (int t = 0; t < 8; t++) {
        int i = base + t;
        v[t] = (i < NN) ? g_cnt[i] : 0;
        s += v[t];
    }
    int x = s;
    #pragma unroll
    for (int o = 1; o < 32; o <<= 1) {
        int y = __shfl_up_sync(0xffffffffu, x, o);
        if (lane >= o) x += y;
    }
    if (lane == 31) ws[warp] = x;
    __syncthreads();
    if (tid == 0) {
        int a = 0;
        #pragma unroll
        for (int w = 0; w < 8; w++) { int t = ws[w]; ws[w] = a; a += t; }
    }
    __syncthreads();
    int excl = ws[warp] + x - s;
    #pragma unroll
    for (int t = 0; t < 8; t++) {
        int i = base + t;
        if (i < NN) g_cnt[i] = excl;
        excl += v[t];
    }
    if (tid == 255) g_bsum[blockIdx.x] = ws[7] + x;
}

__global__ void scan_bsum_kernel() {
    int tid = threadIdx.x;
    int v = (tid < NB) ? g_bsum[tid] : 0;
    int x = v;
    #pragma unroll
    for (int o = 1; o < 32; o <<= 1) {
        int y = __shfl_up_sync(0xffffffffu, x, o);
        if (tid >= o) x += y;
    }
    if (tid < NB) g_bbase[tid] = x - v;
    if (tid == 31) g_bbase[NB] = x;
}

__global__ void finalize_kernel() {
    int i = blockIdx.x * blockDim.x + threadIdx.x;
    if (i < NN) {
        int off = g_cnt[i] + g_bbase[i / SCAN_CHUNK];
        g_off[i] = off;
        g_cur[i] = off;
        g_cnt[i] = 0;
    }
    if (i == 0) g_off[NN] = g_bbase[NB];
}

__global__ void scatter_kernel(const int* __restrict__ src,
                               const int* __restrict__ dst, int E) {
    int i = blockIdx.x * blockDim.x + threadIdx.x;
    if (i < E) {
        int p = atomicAdd(&g_cur[dst[i]], 1);
        g_csr[p] = src[i];
    }
}

// ---------------- GEMM via tf32 tensor-core mma (3xTF32) ----------------
// h[64 rows/block][128] = x@W. 8 warps; warp = 2 m-tiles x 4 n-subtiles (32x32).
// k chunked by 16 (2 mma k-steps). smem strides padded to 20 words -> all
// fragment LDS conflict-free. x split to tf32 hi/lo at fill; W pre-split.
__global__ __launch_bounds__(256) void gemm_mma(
    const float* __restrict__ x,
    const uint32_t* __restrict__ wt_hi, const uint32_t* __restrict__ wt_lo,
    float* __restrict__ h) {
    __shared__ uint32_t xs_hi[64 * 20], xs_lo[64 * 20];
    __shared__ uint32_t ws_hi[128 * 20], ws_lo[128 * 20];
    int tid = threadIdx.x, lane = tid & 31, warp = tid >> 5;
    int g = lane >> 2, t = lane & 3;
    int row0 = blockIdx.x * 64;
    int mh = (warp & 1) * 32;        // m-half: rows mh..mh+31 (2 m16 tiles)
    int nq = (warp >> 1) * 32;       // n-quarter: cols nq..nq+31 (4 n8 tiles)

    float c[2][4][4];
    #pragma unroll
    for (int mi = 0; mi < 2; mi++)
        #pragma unroll
        for (int j = 0; j < 4; j++)
            #pragma unroll
            for (int q = 0; q < 4; q++) c[mi][j][q] = 0.f;

    for (int kc = 0; kc < 8; kc++) {
        __syncthreads();
        // fill x chunk (64 rows x 16 k): 1 float4 per thread, split to hi/lo
        {
            int r = tid >> 2, k4 = tid & 3;
            float4 v = make_float4(0.f, 0.f, 0.f, 0.f);
            if (row0 + r < NN) v = ((const float4*)x)[(row0 + r) * 32 + kc * 4 + k4];
            uint4 hv, lv;
            hv.x = f2tf32(v.x); lv.x = f2tf32(v.x - __uint_as_float(hv.x));
            hv.y = f2tf32(v.y); lv.y = f2tf32(v.y - __uint_as_float(hv.y));
            hv.z = f2tf32(v.z); lv.z = f2tf32(v.z - __uint_as_float(hv.z));
            hv.w = f2tf32(v.w); lv.w = f2tf32(v.w - __uint_as_float(hv.w));
            int o = r * 20 + k4 * 4;
            *(uint4*)&xs_hi[o] = hv;
            *(uint4*)&xs_lo[o] = lv;
        }
        // fill W chunk (128 cols x 16 k): coalesced uint4 copy from chunk-major
        #pragma unroll
        for (int e = 0; e < 2; e++) {
            int i = tid + e * 256;        // 0..511 uint4s
            int cc = i >> 2, k4 = i & 3;
            uint4 vh = ((const uint4*)(wt_hi + kc * 2048))[i];
            uint4 vl = ((const uint4*)(wt_lo + kc * 2048))[i];
            int o = cc * 20 + k4 * 4;
            *(uint4*)&ws_hi[o] = vh;
            *(uint4*)&ws_lo[o] = vl;
        }
        __syncthreads();

        #pragma unroll
        for (int ks = 0; ks < 2; ks++) {
            int k0 = ks * 8 + t;
            uint32_t ah[2][4], al_[2][4];
            #pragma unroll
            for (int mi = 0; mi < 2; mi++) {
                int rb = (mh + mi * 16 + g) * 20 + k0;
                ah[mi][0] = xs_hi[rb];        ah[mi][1] = xs_hi[rb + 160];
                ah[mi][2] = xs_hi[rb + 4];    ah[mi][3] = xs_hi[rb + 164];
                al_[mi][0] = xs_lo[rb];       al_[mi][1] = xs_lo[rb + 160];
                al_[mi][2] = xs_lo[rb + 4];   al_[mi][3] = xs_lo[rb + 164];
            }
            #pragma unroll
            for (int j = 0; j < 4; j++) {
                int cb = (nq + j * 8 + g) * 20 + k0;
                uint32_t bh0 = ws_hi[cb], bh1 = ws_hi[cb + 4];
                uint32_t bl0 = ws_lo[cb], bl1 = ws_lo[cb + 4];
                #pragma unroll
                for (int mi = 0; mi < 2; mi++) {
                    mma_tf32(c[mi][j], ah[mi], bh0, bh1);   // hi*hi
                    mma_tf32(c[mi][j], al_[mi], bh0, bh1);  // lo*hi
                    mma_tf32(c[mi][j], ah[mi], bl0, bl1);   // hi*lo
                }
            }
        }
    }

    // epilogue: write h (float2 per fragment row-pair)
    #pragma unroll
    for (int mi = 0; mi < 2; mi++)
        #pragma unroll
        for (int j = 0; j < 4; j++) {
            int col = nq + j * 8 + 2 * t;
            int r0 = row0 + mh + mi * 16 + g;
            if (r0 < NN)
                *(float2*)&h[r0 * DH + col] = make_float2(c[mi][j][0], c[mi][j][1]);
            if (r0 + 8 < NN)
                *(float2*)&h[(r0 + 8) * DH + col] = make_float2(c[mi][j][2], c[mi][j][3]);
        }
}

// ---------------- attention projections: el/er = h . al/ar per head ----------------
__global__ __launch_bounds__(256) void attn_proj(
    const float* __restrict__ h, const float* __restrict__ al,
    const float* __restrict__ ar, float* __restrict__ el, float* __restrict__ er) {
    int row = blockIdx.x * 8 + (threadIdx.x >> 5);
    if (row >= NN) return;
    int lane = threadIdx.x & 31;
    float4 hv = ((const float4*)h)[row * 32 + lane];
    float4 alv = ((const float4*)al)[lane];
    float4 arv = ((const float4*)ar)[lane];
    float pl = hv.x * alv.x + hv.y * alv.y + hv.z * alv.z + hv.w * alv.w;
    float pr = hv.x * arv.x + hv.y * arv.y + hv.z * arv.z + hv.w * arv.w;
    pl += __shfl_xor_sync(0xffffffffu, pl, 1);
    pl += __shfl_xor_sync(0xffffffffu, pl, 2);
    pr += __shfl_xor_sync(0xffffffffu, pr, 1);
    pr += __shfl_xor_sync(0xffffffffu, pr, 2);
    if ((lane & 3) == 0) {
        el[row * NH + (lane >> 2)] = pl;
        er[row * NH + (lane >> 2)] = pr;
    }
}

// ---------------- fused edge softmax + aggregation: one warp per dst node ----------------
__global__ __launch_bounds__(256) void agg_kernel(
    const float* __restrict__ h, const float* __restrict__ el,
    const float* __restrict__ er, float* __restrict__ out, int act) {
    int w = blockIdx.x * 8 + (threadIdx.x >> 5);
    if (w >= NN) return;
    int lane = threadIdx.x & 31;
    int head = lane >> 2;
    int beg = g_off[w], end = g_off[w + 1];

    float erh = __ldg(&er[w * NH + head]);

    float4 accA = make_float4(0.f, 0.f, 0.f, 0.f);
    float4 accB = make_float4(0.f, 0.f, 0.f, 0.f);
    float zA = 0.f, zB = 0.f;

    int j = beg;
    for (; j + 1 < end; j += 2) {
        int sA = g_csr[j];
        int sB = g_csr[j + 1];
        float vA = __ldg(&el[sA * NH + head]) + erh;
        float vB = __ldg(&el[sB * NH + head]) + erh;
        vA = vA > 0.f ? vA : 0.2f * vA;
        vB = vB > 0.f ? vB : 0.2f * vB;
        float aA = __expf(vA);
        float aB = __expf(vB);
        float4 hA = ((const float4*)h)[sA * 32 + lane];
        float4 hB = ((const float4*)h)[sB * 32 + lane];
        zA += aA;
        zB += aB;
        accA.x = fmaf(aA, hA.x, accA.x);
        accA.y = fmaf(aA, hA.y, accA.y);
        accA.z = fmaf(aA, hA.z, accA.z);
        accA.w = fmaf(aA, hA.w, accA.w);
        accB.x = fmaf(aB, hB.x, accB.x);
        accB.y = fmaf(aB, hB.y, accB.y);
        accB.z = fmaf(aB, hB.z, accB.z);
        accB.w = fmaf(aB, hB.w, accB.w);
    }
    if (j < end) {
        int s = g_csr[j];
        float v = __ldg(&el[s * NH + head]) + erh;
        v = v > 0.f ? v : 0.2f * v;
        float a = __expf(v);
        float4 hv = ((const float4*)h)[s * 32 + lane];
        zA += a;
        accA.x = fmaf(a, hv.x, accA.x);
        accA.y = fmaf(a, hv.y, accA.y);
        accA.z = fmaf(a, hv.z, accA.z);
        accA.w = fmaf(a, hv.w, accA.w);
    }

    float z = zA + zB;
    float4 acc = make_float4(accA.x + accB.x, accA.y + accB.y,
                             accA.z + accB.z, accA.w + accB.w);
    float invz = (end > beg) ? 1.0f / z : 0.f;   // deg-0 -> output 0 (matches ref)
    acc.x *= invz; acc.y *= invz; acc.z *= invz; acc.w *= invz;

    if (act) {
        acc.x = acc.x > 0.f ? acc.x : 0.01f * acc.x;
        acc.y = acc.y > 0.f ? acc.y : 0.01f * acc.y;
        acc.z = acc.z > 0.f ? acc.z : 0.01f * acc.z;
        acc.w = acc.w > 0.f ? acc.w : 0.01f * acc.w;
    }
    ((float4*)out)[w * 32 + lane] = acc;
}

// ---------------- launch ----------------
extern "C" void kernel_launch(void* const* d_in, const int* in_sizes, int n_in,
                              void* d_out, int out_size) {
    const float* x   = (const float*)d_in[0];
    const int*   src = (const int*)d_in[1];
    const int*   dst = (const int*)d_in[2];
    const float* W1  = (const float*)d_in[3];
    const float* al1 = (const float*)d_in[4];
    const float* ar1 = (const float*)d_in[5];
    const float* W2  = (const float*)d_in[6];
    const float* al2 = (const float*)d_in[7];
    const float* ar2 = (const float*)d_in[8];
    float* out = (float*)d_out;
    int E = in_sizes[1];

    float *ph, *po, *pel, *per;
    uint32_t *pwh, *pwl;
    cudaGetSymbolAddress((void**)&ph,  g_h);
    cudaGetSymbolAddress((void**)&po,  g_o);
    cudaGetSymbolAddress((void**)&pel, g_el);
    cudaGetSymbolAddress((void**)&per, g_er);
    cudaGetSymbolAddress((void**)&pwh, g_wt_hi);
    cudaGetSymbolAddress((void**)&pwl, g_wt_lo);

    const int GB = (NN + 63) / 64;   // gemm blocks

    // layer 1 + CSR build (gemm1 at my launch idx 3 -> ncu -s5 captures it)
    w_split_kernel<<<64, 256>>>(W1, pwh, pwl);                          // 0
    hist_kernel<<<(E + 255) / 256, 256>>>(dst, E);                      // 1
    partial_scan_kernel<<<NB, 256>>>();                                 // 2
    gemm_mma<<<GB, 256>>>(x, pwh, pwl, ph);                             // 3 (ncu)
    scan_bsum_kernel<<<1, 32>>>();                                      // 4
    attn_proj<<<(NN + 7) / 8, 256>>>(ph, al1, ar1, pel, per);           // 5
    finalize_kernel<<<(NN + 255) / 256, 256>>>();                       // 6
    scatter_kernel<<<(E + 255) / 256, 256>>>(src, dst, E);              // 7
    agg_kernel<<<NN / 8, 256>>>(ph, pel, per, po, 1);                   // 8

    // layer 2
    w_split_kernel<<<64, 256>>>(W2, pwh, pwl);                          // 9
    gemm_mma<<<GB, 256>>>(po, pwh, pwl, ph);                            // 10
    attn_proj<<<(NN + 7) / 8, 256>>>(ph, al2, ar2, pel, per);           // 11
    agg_kernel<<<NN / 8, 256>>>(ph, pel, per, out, 0);                  // 12
}

// round 9
// speedup vs baseline: 1.4958x; 1.0769x over previous
#include <cuda_runtime.h>
#include <stdint.h>

#define NN 50000
#define EE 800000
#define DH 128
#define NH 8
#define SCAN_CHUNK 2048
#define NB ((NN + SCAN_CHUNK - 1) / SCAN_CHUNK)   // 25 scan blocks

// ---------------- device scratch (no cudaMalloc allowed) ----------------
__device__ float    g_h[NN * DH];     // per-layer projected features h = x@W
__device__ float    g_o[NN * DH];     // layer-1 output (activated)
__device__ float    g_el[NN * NH];    // attention left logits
__device__ float    g_er[NN * NH];    // attention right logits
__device__ int      g_off[NN + 1];    // CSR row offsets (by dst)
__device__ int      g_cur[NN];        // scatter cursors
__device__ int      g_cnt[NN];        // in-degree histogram
__device__ int      g_csr[EE];        // src node per CSR slot
__device__ int      g_bsum[NB];
__device__ int      g_bbase[NB + 1];
__device__ uint32_t g_wt_hi[128 * 128];  // W split, chunk-major [kc][c][kk]
__device__ uint32_t g_wt_lo[128 * 128];

// ---------------- tf32 helpers ----------------
__device__ __forceinline__ uint32_t f2tf32(float f) {
    uint32_t r;
    asm("cvt.rna.tf32.f32 %0, %1;" : "=r"(r) : "f"(f));
    return r;
}
// D += A(16x8,row) * B(8x8,col), tf32 inputs, f32 accum
__device__ __forceinline__ void mma_tf32(float* c, const uint32_t* a,
                                         uint32_t b0, uint32_t b1) {
    asm("mma.sync.aligned.m16n8k8.row.col.f32.tf32.tf32.f32 "
        "{%0,%1,%2,%3}, {%4,%5,%6,%7}, {%8,%9}, {%0,%1,%2,%3};"
        : "+f"(c[0]), "+f"(c[1]), "+f"(c[2]), "+f"(c[3])
        : "r"(a[0]), "r"(a[1]), "r"(a[2]), "r"(a[3]), "r"(b0), "r"(b1));
}

// ---------------- W pre-split: fp32 -> tf32 hi/lo, chunk-major ----------------
// In: W[k][c] row-major 128x128. Out layout: [(k/16)][c][k%16] (2048 words/chunk).
__global__ void w_split_kernel(const float* __restrict__ W,
                               uint32_t* __restrict__ hi, uint32_t* __restrict__ lo) {
    int i = blockIdx.x * 256 + threadIdx.x;   // 16384 elements
    int k = i >> 7, c = i & 127;
    float v = W[i];
    uint32_t hb = f2tf32(v);
    float lres = v - __uint_as_float(hb);
    int o = (k >> 4) * 2048 + c * 16 + (k & 15);
    hi[o] = hb;
    lo[o] = f2tf32(lres);
}

// ---------------- CSR build ----------------
__global__ void hist_kernel(const int* __restrict__ dst, int E) {
    int i = blockIdx.x * blockDim.x + threadIdx.x;
    if (i < E) atomicAdd(&g_cnt[dst[i]], 1);
}

__global__ __launch_bounds__(256) void partial_scan_kernel() {
    __shared__ int ws[8];
    int tid = threadIdx.x, lane = tid & 31, warp = tid >> 5;
    int base = blockIdx.x * SCAN_CHUNK + tid * 8;
    int v[8], s = 0;
    #pragma unroll
    for (int t = 0; t < 8; t++) {
        int i = base + t;
        v[t] = (i < NN) ? g_cnt[i] : 0;
        s += v[t];
    }
    int x = s;
    #pragma unroll
    for (int o = 1; o < 32; o <<= 1) {
        int y = __shfl_up_sync(0xffffffffu, x, o);
        if (lane >= o) x += y;
    }
    if (lane == 31) ws[warp] = x;
    __syncthreads();
    if (tid == 0) {
        int a = 0;
        #pragma unroll
        for (int w = 0; w < 8; w++) { int t = ws[w]; ws[w] = a; a += t; }
    }
    __syncthreads();
    int excl = ws[warp] + x - s;
    #pragma unroll
    for (int t = 0; t < 8; t++) {
        int i = base + t;
        if (i < NN) g_cnt[i] = excl;
        excl += v[t];
    }
    if (tid == 255) g_bsum[blockIdx.x] = ws[7] + x;
}

__global__ void scan_bsum_kernel() {
    int tid = threadIdx.x;
    int v = (tid < NB) ? g_bsum[tid] : 0;
    int x = v;
    #pragma unroll
    for (int o = 1; o < 32; o <<= 1) {
        int y = __shfl_up_sync(0xffffffffu, x, o);
        if (tid >= o) x += y;
    }
    if (tid < NB) g_bbase[tid] = x - v;
    if (tid == 31) g_bbase[NB] = x;
}

__global__ void finalize_kernel() {
    int i = blockIdx.x * blockDim.x + threadIdx.x;
    if (i < NN) {
        int off = g_cnt[i] + g_bbase[i / SCAN_CHUNK];
        g_off[i] = off;
        g_cur[i] = off;
        g_cnt[i] = 0;
    }
    if (i == 0) g_off[NN] = g_bbase[NB];
}

__global__ void scatter_kernel(const int* __restrict__ src,
                               const int* __restrict__ dst, int E) {
    int i = blockIdx.x * blockDim.x + threadIdx.x;
    if (i < E) {
        int p = atomicAdd(&g_cur[dst[i]], 1);
        g_csr[p] = src[i];
    }
}

// ---------------- GEMM via tf32 tensor-core mma (3xTF32) ----------------
// h[64 rows/block][128] = x@W. 8 warps; warp = 2 m-tiles x 4 n-subtiles (32x32).
// k chunked by 16 (2 mma k-steps). smem strides padded to 20 words -> all
// fragment LDS conflict-free. x split to tf32 hi/lo at fill; W pre-split.
__global__ __launch_bounds__(256) void gemm_mma(
    const float* __restrict__ x,
    const uint32_t* __restrict__ wt_hi, const uint32_t* __restrict__ wt_lo,
    float* __restrict__ h) {
    __shared__ uint32_t xs_hi[64 * 20], xs_lo[64 * 20];
    __shared__ uint32_t ws_hi[128 * 20], ws_lo[128 * 20];
    int tid = threadIdx.x, lane = tid & 31, warp = tid >> 5;
    int g = lane >> 2, t = lane & 3;
    int row0 = blockIdx.x * 64;
    int mh = (warp & 1) * 32;        // m-half: rows mh..mh+31 (2 m16 tiles)
    int nq = (warp >> 1) * 32;       // n-quarter: cols nq..nq+31 (4 n8 tiles)

    float c[2][4][4];
    #pragma unroll
    for (int mi = 0; mi < 2; mi++)
        #pragma unroll
        for (int j = 0; j < 4; j++)
            #pragma unroll
            for (int q = 0; q < 4; q++) c[mi][j][q] = 0.f;

    for (int kc = 0; kc < 8; kc++) {
        __syncthreads();
        // fill x chunk (64 rows x 16 k): 1 float4 per thread, split to hi/lo
        {
            int r = tid >> 2, k4 = tid & 3;
            float4 v = make_float4(0.f, 0.f, 0.f, 0.f);
            if (row0 + r < NN) v = ((const float4*)x)[(row0 + r) * 32 + kc * 4 + k4];
            uint4 hv, lv;
            hv.x = f2tf32(v.x); lv.x = f2tf32(v.x - __uint_as_float(hv.x));
            hv.y = f2tf32(v.y); lv.y = f2tf32(v.y - __uint_as_float(hv.y));
            hv.z = f2tf32(v.z); lv.z = f2tf32(v.z - __uint_as_float(hv.z));
            hv.w = f2tf32(v.w); lv.w = f2tf32(v.w - __uint_as_float(hv.w));
            int o = r * 20 + k4 * 4;
            *(uint4*)&xs_hi[o] = hv;
            *(uint4*)&xs_lo[o] = lv;
        }
        // fill W chunk (128 cols x 16 k): coalesced uint4 copy from chunk-major
        #pragma unroll
        for (int e = 0; e < 2; e++) {
            int i = tid + e * 256;        // 0..511 uint4s
            int cc = i >> 2, k4 = i & 3;
            uint4 vh = ((const uint4*)(wt_hi + kc * 2048))[i];
            uint4 vl = ((const uint4*)(wt_lo + kc * 2048))[i];
            int o = cc * 20 + k4 * 4;
            *(uint4*)&ws_hi[o] = vh;
            *(uint4*)&ws_lo[o] = vl;
        }
        __syncthreads();

        #pragma unroll
        for (int ks = 0; ks < 2; ks++) {
            int k0 = ks * 8 + t;
            uint32_t ah[2][4], al_[2][4];
            #pragma unroll
            for (int mi = 0; mi < 2; mi++) {
                int rb = (mh + mi * 16 + g) * 20 + k0;
                ah[mi][0] = xs_hi[rb];        ah[mi][1] = xs_hi[rb + 160];
                ah[mi][2] = xs_hi[rb + 4];    ah[mi][3] = xs_hi[rb + 164];
                al_[mi][0] = xs_lo[rb];       al_[mi][1] = xs_lo[rb + 160];
                al_[mi][2] = xs_lo[rb + 4];   al_[mi][3] = xs_lo[rb + 164];
            }
            #pragma unroll
            for (int j = 0; j < 4; j++) {
                int cb = (nq + j * 8 + g) * 20 + k0;
                uint32_t bh0 = ws_hi[cb], bh1 = ws_hi[cb + 4];
                uint32_t bl0 = ws_lo[cb], bl1 = ws_lo[cb + 4];
                #pragma unroll
                for (int mi = 0; mi < 2; mi++) {
                    mma_tf32(c[mi][j], ah[mi], bh0, bh1);   // hi*hi
                    mma_tf32(c[mi][j], al_[mi], bh0, bh1);  // lo*hi
                    mma_tf32(c[mi][j], ah[mi], bl0, bl1);   // hi*lo
                }
            }
        }
    }

    // epilogue: write h (float2 per fragment row-pair)
    #pragma unroll
    for (int mi = 0; mi < 2; mi++)
        #pragma unroll
        for (int j = 0; j < 4; j++) {
            int col = nq + j * 8 + 2 * t;
            int r0 = row0 + mh + mi * 16 + g;
            if (r0 < NN)
                *(float2*)&h[r0 * DH + col] = make_float2(c[mi][j][0], c[mi][j][1]);
            if (r0 + 8 < NN)
                *(float2*)&h[(r0 + 8) * DH + col] = make_float2(c[mi][j][2], c[mi][j][3]);
        }
}

// ---------------- attention projections: el/er = h . al/ar per head ----------------
__global__ __launch_bounds__(256) void attn_proj(
    const float* __restrict__ h, const float* __restrict__ al,
    const float* __restrict__ ar, float* __restrict__ el, float* __restrict__ er) {
    int row = blockIdx.x * 8 + (threadIdx.x >> 5);
    if (row >= NN) return;
    int lane = threadIdx.x & 31;
    float4 hv = ((const float4*)h)[row * 32 + lane];
    float4 alv = ((const float4*)al)[lane];
    float4 arv = ((const float4*)ar)[lane];
    float pl = hv.x * alv.x + hv.y * alv.y + hv.z * alv.z + hv.w * alv.w;
    float pr = hv.x * arv.x + hv.y * arv.y + hv.z * arv.z + hv.w * arv.w;
    pl += __shfl_xor_sync(0xffffffffu, pl, 1);
    pl += __shfl_xor_sync(0xffffffffu, pl, 2);
    pr += __shfl_xor_sync(0xffffffffu, pr, 1);
    pr += __shfl_xor_sync(0xffffffffu, pr, 2);
    if ((lane & 3) == 0) {
        el[row * NH + (lane >> 2)] = pl;
        er[row * NH + (lane >> 2)] = pr;
    }
}

// ---------------- fused edge softmax + aggregation: one warp per dst node ----------------
__global__ __launch_bounds__(256) void agg_kernel(
    const float* __restrict__ h, const float* __restrict__ el,
    const float* __restrict__ er, float* __restrict__ out, int act) {
    int w = blockIdx.x * 8 + (threadIdx.x >> 5);
    if (w >= NN) return;
    int lane = threadIdx.x & 31;
    int head = lane >> 2;
    int beg = g_off[w], end = g_off[w + 1];

    float erh = __ldg(&er[w * NH + head]);

    float4 accA = make_float4(0.f, 0.f, 0.f, 0.f);
    float4 accB = make_float4(0.f, 0.f, 0.f, 0.f);
    float zA = 0.f, zB = 0.f;

    int j = beg;
    for (; j + 1 < end; j += 2) {
        int sA = g_csr[j];
        int sB = g_csr[j + 1];
        float vA = __ldg(&el[sA * NH + head]) + erh;
        float vB = __ldg(&el[sB * NH + head]) + erh;
        vA = vA > 0.f ? vA : 0.2f * vA;
        vB = vB > 0.f ? vB : 0.2f * vB;
        float aA = __expf(vA);
        float aB = __expf(vB);
        float4 hA = ((const float4*)h)[sA * 32 + lane];
        float4 hB = ((const float4*)h)[sB * 32 + lane];
        zA += aA;
        zB += aB;
        accA.x = fmaf(aA, hA.x, accA.x);
        accA.y = fmaf(aA, hA.y, accA.y);
        accA.z = fmaf(aA, hA.z, accA.z);
        accA.w = fmaf(aA, hA.w, accA.w);
        accB.x = fmaf(aB, hB.x, accB.x);
        accB.y = fmaf(aB, hB.y, accB.y);
        accB.z = fmaf(aB, hB.z, accB.z);
        accB.w = fmaf(aB, hB.w, accB.w);
    }
    if (j < end) {
        int s = g_csr[j];
        float v = __ldg(&el[s * NH + head]) + erh;
        v = v > 0.f ? v : 0.2f * v;
        float a = __expf(v);
        float4 hv = ((const float4*)h)[s * 32 + lane];
        zA += a;
        accA.x = fmaf(a, hv.x, accA.x);
        accA.y = fmaf(a, hv.y, accA.y);
        accA.z = fmaf(a, hv.z, accA.z);
        accA.w = fmaf(a, hv.w, accA.w);
    }

    float z = zA + zB;
    float4 acc = make_float4(accA.x + accB.x, accA.y + accB.y,
                             accA.z + accB.z, accA.w + accB.w);
    float invz = (end > beg) ? 1.0f / z : 0.f;   // deg-0 -> output 0 (matches ref)
    acc.x *= invz; acc.y *= invz; acc.z *= invz; acc.w *= invz;

    if (act) {
        acc.x = acc.x > 0.f ? acc.x : 0.01f * acc.x;
        acc.y = acc.y > 0.f ? acc.y : 0.01f * acc.y;
        acc.z = acc.z > 0.f ? acc.z : 0.01f * acc.z;
        acc.w = acc.w > 0.f ? acc.w : 0.01f * acc.w;
    }
    ((float4*)out)[w * 32 + lane] = acc;
}

// ---------------- launch ----------------
// Two-stream graph: CSR build (src/dst only) runs concurrent with layer-1
// compute (x/W1 only); join before agg1. wsplit2 overlaps agg1 on the side
// stream (after gemm1 releases g_wt). Event fork/join is graph-capturable;
// streams/events are host-side resources (no device memory allocation).
extern "C" void kernel_launch(void* const* d_in, const int* in_sizes, int n_in,
                              void* d_out, int out_size) {
    const float* x   = (const float*)d_in[0];
    const int*   src = (const int*)d_in[1];
    const int*   dst = (const int*)d_in[2];
    const float* W1  = (const float*)d_in[3];
    const float* al1 = (const float*)d_in[4];
    const float* ar1 = (const float*)d_in[5];
    const float* W2  = (const float*)d_in[6];
    const float* al2 = (const float*)d_in[7];
    const float* ar2 = (const float*)d_in[8];
    float* out = (float*)d_out;
    int E = in_sizes[1];

    float *ph, *po, *pel, *per;
    uint32_t *pwh, *pwl;
    cudaGetSymbolAddress((void**)&ph,  g_h);
    cudaGetSymbolAddress((void**)&po,  g_o);
    cudaGetSymbolAddress((void**)&pel, g_el);
    cudaGetSymbolAddress((void**)&per, g_er);
    cudaGetSymbolAddress((void**)&pwh, g_wt_hi);
    cudaGetSymbolAddress((void**)&pwl, g_wt_lo);

    // one-time host-side resources (no device memory involved)
    static cudaStream_t s2 = nullptr;
    static cudaEvent_t ev_fork = nullptr, ev_csr = nullptr,
                       ev_gemm1 = nullptr, ev_w2 = nullptr;
    if (s2 == nullptr) {
        cudaStreamCreateWithFlags(&s2, cudaStreamNonBlocking);
        cudaEventCreateWithFlags(&ev_fork,  cudaEventDisableTiming);
        cudaEventCreateWithFlags(&ev_csr,   cudaEventDisableTiming);
        cudaEventCreateWithFlags(&ev_gemm1, cudaEventDisableTiming);
        cudaEventCreateWithFlags(&ev_w2,    cudaEventDisableTiming);
    }

    const int GB = (NN + 63) / 64;   // gemm blocks

    // fork: side stream joins the capture via event on the origin stream
    cudaEventRecord(ev_fork, 0);
    cudaStreamWaitEvent(s2, ev_fork, 0);

    // side stream: CSR build chain (independent of layer-1 compute)
    hist_kernel<<<(E + 255) / 256, 256, 0, s2>>>(dst, E);
    partial_scan_kernel<<<NB, 256, 0, s2>>>();
    scan_bsum_kernel<<<1, 32, 0, s2>>>();
    finalize_kernel<<<(NN + 255) / 256, 256, 0, s2>>>();
    scatter_kernel<<<(E + 255) / 256, 256, 0, s2>>>(src, dst, E);
    cudaEventRecord(ev_csr, s2);

    // main stream: layer-1 compute
    w_split_kernel<<<64, 256>>>(W1, pwh, pwl);
    gemm_mma<<<GB, 256>>>(x, pwh, pwl, ph);
    cudaEventRecord(ev_gemm1, 0);            // g_wt free after gemm1
    attn_proj<<<(NN + 7) / 8, 256>>>(ph, al1, ar1, pel, per);

    // side stream: wsplit2 overlaps agg1 (needs gemm1 done + CSR chain order)
    cudaStreamWaitEvent(s2, ev_gemm1, 0);
    w_split_kernel<<<64, 256, 0, s2>>>(W2, pwh, pwl);
    cudaEventRecord(ev_w2, s2);

    // join: agg1 needs the CSR
    cudaStreamWaitEvent(0, ev_csr, 0);
    agg_kernel<<<NN / 8, 256>>>(ph, pel, per, po, 1);

    // layer 2 (needs wsplit2)
    cudaStreamWaitEvent(0, ev_w2, 0);
    gemm_mma<<<GB, 256>>>(po, pwh, pwl, ph);
    attn_proj<<<(NN + 7) / 8, 256>>>(ph, al2, ar2, pel, per);
    agg_kernel<<<NN / 8, 256>>>(ph, pel, per, out, 0);
}

// round 11
// speedup vs baseline: 1.7031x; 1.1386x over previous
#include <cuda_runtime.h>
#include <cuda_bf16.h>
#include <stdint.h>

#define NN 50000
#define EE 800000
#define DH 128
#define NH 8
#define SCAN_CHUNK 2048
#define NB ((NN + SCAN_CHUNK - 1) / SCAN_CHUNK)   // 25 scan blocks

// ---------------- device scratch (no cudaMalloc allowed) ----------------
__device__ float    g_h[NN * DH];     // per-layer projected features h = x@W
__device__ float    g_o[NN * DH];     // layer-1 output (activated)
__device__ float    g_el[NN * NH];    // attention left logits
__device__ float    g_er[NN * NH];    // attention right logits
__device__ int      g_off[NN + 1];    // CSR row offsets (by dst)
__device__ int      g_cur[NN];        // scatter cursors
__device__ int      g_cnt[NN];        // in-degree histogram
__device__ int      g_csr[EE];        // src node per CSR slot
__device__ int      g_bsum[NB];
__device__ int      g_bbase[NB + 1];
// W split to bf16 hi/lo, fragment-layout chunk-major:
// u32 words, pair (k=2p,2p+1) of column c in chunk kc:
//   wt[((kc*128 + c)*8 + p)*2 + 0] = (bf16 hi of k0 | hi of k1 << 16)
//   wt[((kc*128 + c)*8 + p)*2 + 1] = (bf16 lo of k0 | lo of k1 << 16)
__device__ uint32_t g_wt[128 * 128];  // 16384 u32 = 64KB

// ---------------- bf16 helpers ----------------
__device__ __forceinline__ uint32_t pack_bf16(float a, float b) {
    __nv_bfloat162 t = __floats2bfloat162_rn(a, b);   // .x = a (low), .y = b (high)
    return *(uint32_t*)&t;
}
__device__ __forceinline__ float bf16_hi(float v) {
    return __bfloat162float(__float2bfloat16_rn(v));
}
// D += A(16x16) * B(16x8), bf16 inputs, f32 accum
__device__ __forceinline__ void mma_bf16(float* c, const uint32_t* a,
                                         uint32_t b0, uint32_t b1) {
    asm("mma.sync.aligned.m16n8k16.row.col.f32.bf16.bf16.f32 "
        "{%0,%1,%2,%3}, {%4,%5,%6,%7}, {%8,%9}, {%0,%1,%2,%3};"
        : "+f"(c[0]), "+f"(c[1]), "+f"(c[2]), "+f"(c[3])
        : "r"(a[0]), "r"(a[1]), "r"(a[2]), "r"(a[3]), "r"(b0), "r"(b1));
}

// ---------------- W pre-split: fp32 -> bf16 hi/lo pairs, chunk-major ----------------
__global__ void w_split_kernel(const float* __restrict__ W, uint32_t* __restrict__ wt) {
    int i = blockIdx.x * 256 + threadIdx.x;   // 8192 pairs
    int c = (i >> 3) & 127;
    int kc = i >> 10;
    int p = i & 7;
    int k0 = kc * 16 + 2 * p;
    float v0 = W[k0 * 128 + c];
    float v1 = W[(k0 + 1) * 128 + c];
    float h0 = bf16_hi(v0), h1 = bf16_hi(v1);
    wt[i * 2]     = pack_bf16(h0, h1);
    wt[i * 2 + 1] = pack_bf16(v0 - h0, v1 - h1);
}

// ---------------- CSR build ----------------
__global__ void hist_kernel(const int* __restrict__ dst, int E) {
    int i = blockIdx.x * blockDim.x + threadIdx.x;
    if (i < E) atomicAdd(&g_cnt[dst[i]], 1);
}

__global__ __launch_bounds__(256) void partial_scan_kernel() {
    __shared__ int ws[8];
    int tid = threadIdx.x, lane = tid & 31, warp = tid >> 5;
    int base = blockIdx.x * SCAN_CHUNK + tid * 8;
    int v[8], s = 0;
    #pragma unroll
    for (int t = 0; t < 8; t++) {
        int i = base + t;
        v[t] = (i < NN) ? g_cnt[i] : 0;
        s += v[t];
    }
    int x = s;
    #pragma unroll
    for (int o = 1; o < 32; o <<= 1) {
        int y = __shfl_up_sync(0xffffffffu, x, o);
        if (lane >= o) x += y;
    }
    if (lane == 31) ws[warp] = x;
    __syncthreads();
    if (tid == 0) {
        int a = 0;
        #pragma unroll
        for (int w = 0; w < 8; w++) { int t = ws[w]; ws[w] = a; a += t; }
    }
    __syncthreads();
    int excl = ws[warp] + x - s;
    #pragma unroll
    for (int t = 0; t < 8; t++) {
        int i = base + t;
        if (i < NN) g_cnt[i] = excl;
        excl += v[t];
    }
    if (tid == 255) g_bsum[blockIdx.x] = ws[7] + x;
}

__global__ void scan_bsum_kernel() {
    int tid = threadIdx.x;
    int v = (tid < NB) ? g_bsum[tid] : 0;
    int x = v;
    #pragma unroll
    for (int o = 1; o < 32; o <<= 1) {
        int y = __shfl_up_sync(0xffffffffu, x, o);
        if (tid >= o) x += y;
    }
    if (tid < NB) g_bbase[tid] = x - v;
    if (tid == 31) g_bbase[NB] = x;
}

__global__ void finalize_kernel() {
    int i = blockIdx.x * blockDim.x + threadIdx.x;
    if (i < NN) {
        int off = g_cnt[i] + g_bbase[i / SCAN_CHUNK];
        g_off[i] = off;
        g_cur[i] = off;
        g_cnt[i] = 0;
    }
    if (i == 0) g_off[NN] = g_bbase[NB];
}

__global__ void scatter_kernel(const int* __restrict__ src,
                               const int* __restrict__ dst, int E) {
    int i = blockIdx.x * blockDim.x + threadIdx.x;
    if (i < E) {
        int p = atomicAdd(&g_cur[dst[i]], 1);
        g_csr[p] = src[i];
    }
}

// ---------------- GEMM via bf16 tensor-core mma (3xBF16 compensation) ----------------
// h[64 rows/block][128] = x@W. 8 warps; warp = 2 m16 tiles x 4 n8 tiles.
// k chunked by 16 (one mma k-step). hi/lo interleaved as (hi,lo) u32 pairs in
// smem -> every fragment load is one LDS.64. Row stride 12 u64 (12g+t distinct
// mod 16 per phase -> conflict-free). D += Ah*Bh + Al*Bh + Ah*Bl.
__global__ __launch_bounds__(256) void gemm_mma(
    const float* __restrict__ x, const uint32_t* __restrict__ wt,
    float* __restrict__ h) {
    __shared__ uint32_t xs[64 * 24];    // 6KB:  row stride 12 u64 (24 u32)
    __shared__ uint32_t ws[128 * 24];   // 12KB: col stride 12 u64
    int tid = threadIdx.x, lane = tid & 31, warp = tid >> 5;
    int g = lane >> 2, t = lane & 3;
    int row0 = blockIdx.x * 64;
    int mh = (warp & 1) * 32;        // m-half: rows mh..mh+31 (2 m16 tiles)
    int nq = (warp >> 1) * 32;       // n-quarter: cols nq..nq+31 (4 n8 tiles)
    const uint2* xs2 = (const uint2*)xs;
    const uint2* ws2 = (const uint2*)ws;

    float c[2][4][4];
    #pragma unroll
    for (int mi = 0; mi < 2; mi++)
        #pragma unroll
        for (int j = 0; j < 4; j++)
            #pragma unroll
            for (int q = 0; q < 4; q++) c[mi][j][q] = 0.f;

    for (int kc = 0; kc < 8; kc++) {
        __syncthreads();
        // fill x chunk (64 rows x 16 k): 1 float4/thread -> bf16 hi/lo pairs
        {
            int r = tid >> 2, q = tid & 3;
            float4 v = make_float4(0.f, 0.f, 0.f, 0.f);
            if (row0 + r < NN) v = ((const float4*)x)[(row0 + r) * 32 + kc * 4 + q];
            float hx = bf16_hi(v.x), hy = bf16_hi(v.y);
            float hz = bf16_hi(v.z), hw = bf16_hi(v.w);
            uint4 o;
            o.x = pack_bf16(hx, hy);               // hi pair 2q
            o.y = pack_bf16(v.x - hx, v.y - hy);   // lo pair 2q
            o.z = pack_bf16(hz, hw);               // hi pair 2q+1
            o.w = pack_bf16(v.z - hz, v.w - hw);   // lo pair 2q+1
            ((uint4*)xs)[r * 6 + q] = o;           // u32 idx r*24 + 4q
        }
        // fill W chunk (128 cols x 16 k, hi/lo interleaved): coalesced uint4 copy
        #pragma unroll
        for (int e = 0; e < 2; e++) {
            int i = tid + e * 256;                 // 0..511 uint4s (2 pairs each)
            int n = i >> 2, pp = i & 3;            // pair-pair index
            uint4 v = ((const uint4*)(wt + kc * 2048))[i];
            ((uint4*)ws)[n * 6 + pp] = v;          // u32 idx n*24 + 4*pp
        }
        __syncthreads();

        uint32_t ah[2][4], al_[2][4];
        #pragma unroll
        for (int mi = 0; mi < 2; mi++) {
            int mb = (mh + mi * 16 + g) * 12;
            uint2 v0 = xs2[mb + t];            // (m=g,    pair t)
            uint2 v1 = xs2[mb + 96 + t];       // (m=g+8,  pair t)   (+8 rows*12)
            uint2 v2 = xs2[mb + 4 + t];        // (m=g,    pair t+4)
            uint2 v3 = xs2[mb + 100 + t];      // (m=g+8,  pair t+4)
            ah[mi][0] = v0.x; al_[mi][0] = v0.y;
            ah[mi][1] = v1.x; al_[mi][1] = v1.y;
            ah[mi][2] = v2.x; al_[mi][2] = v2.y;
            ah[mi][3] = v3.x; al_[mi][3] = v3.y;
        }
        #pragma unroll
        for (int j = 0; j < 4; j++) {
            int cb = (nq + j * 8 + g) * 12;
            uint2 b0 = ws2[cb + t];            // (n, pair t):   hi,lo
            uint2 b1 = ws2[cb + 4 + t];        // (n, pair t+4): hi,lo
            #pragma unroll
            for (int mi = 0; mi < 2; mi++) {
                mma_bf16(c[mi][j], ah[mi],  b0.x, b1.x);   // hi*hi
                mma_bf16(c[mi][j], al_[mi], b0.x, b1.x);   // lo*hi
                mma_bf16(c[mi][j], ah[mi],  b0.y, b1.y);   // hi*lo
            }
        }
    }

    // epilogue: write h (float2 per fragment row-pair)
    #pragma unroll
    for (int mi = 0; mi < 2; mi++)
        #pragma unroll
        for (int j = 0; j < 4; j++) {
            int col = nq + j * 8 + 2 * t;
            int r0 = row0 + mh + mi * 16 + g;
            if (r0 < NN)
                *(float2*)&h[r0 * DH + col] = make_float2(c[mi][j][0], c[mi][j][1]);
            if (r0 + 8 < NN)
                *(float2*)&h[(r0 + 8) * DH + col] = make_float2(c[mi][j][2], c[mi][j][3]);
        }
}

// ---------------- attention projections: el/er = h . al/ar per head ----------------
__global__ __launch_bounds__(256) void attn_proj(
    const float* __restrict__ h, const float* __restrict__ al,
    const float* __restrict__ ar, float* __restrict__ el, float* __restrict__ er) {
    int row = blockIdx.x * 8 + (threadIdx.x >> 5);
    if (row >= NN) return;
    int lane = threadIdx.x & 31;
    float4 hv = ((const float4*)h)[row * 32 + lane];
    float4 alv = ((const float4*)al)[lane];
    float4 arv = ((const float4*)ar)[lane];
    float pl = hv.x * alv.x + hv.y * alv.y + hv.z * alv.z + hv.w * alv.w;
    float pr = hv.x * arv.x + hv.y * arv.y + hv.z * arv.z + hv.w * arv.w;
    pl += __shfl_xor_sync(0xffffffffu, pl, 1);
    pl += __shfl_xor_sync(0xffffffffu, pl, 2);
    pr += __shfl_xor_sync(0xffffffffu, pr, 1);
    pr += __shfl_xor_sync(0xffffffffu, pr, 2);
    if ((lane & 3) == 0) {
        el[row * NH + (lane >> 2)] = pl;
        er[row * NH + (lane >> 2)] = pr;
    }
}

// ---------------- fused edge softmax + aggregation: one warp per dst node ----------------
__global__ __launch_bounds__(256) void agg_kernel(
    const float* __restrict__ h, const float* __restrict__ el,
    const float* __restrict__ er, float* __restrict__ out, int act) {
    int w = blockIdx.x * 8 + (threadIdx.x >> 5);
    if (w >= NN) return;
    int lane = threadIdx.x & 31;
    int head = lane >> 2;
    int beg = g_off[w], end = g_off[w + 1];

    float erh = __ldg(&er[w * NH + head]);

    float4 accA = make_float4(0.f, 0.f, 0.f, 0.f);
    float4 accB = make_float4(0.f, 0.f, 0.f, 0.f);
    float zA = 0.f, zB = 0.f;

    int j = beg;
    for (; j + 1 < end; j += 2) {
        int sA = g_csr[j];
        int sB = g_csr[j + 1];
        float vA = __ldg(&el[sA * NH + head]) + erh;
        float vB = __ldg(&el[sB * NH + head]) + erh;
        vA = vA > 0.f ? vA : 0.2f * vA;
        vB = vB > 0.f ? vB : 0.2f * vB;
        float aA = __expf(vA);
        float aB = __expf(vB);
        float4 hA = ((const float4*)h)[sA * 32 + lane];
        float4 hB = ((const float4*)h)[sB * 32 + lane];
        zA += aA;
        zB += aB;
        accA.x = fmaf(aA, hA.x, accA.x);
        accA.y = fmaf(aA, hA.y, accA.y);
        accA.z = fmaf(aA, hA.z, accA.z);
        accA.w = fmaf(aA, hA.w, accA.w);
        accB.x = fmaf(aB, hB.x, accB.x);
        accB.y = fmaf(aB, hB.y, accB.y);
        accB.z = fmaf(aB, hB.z, accB.z);
        accB.w = fmaf(aB, hB.w, accB.w);
    }
    if (j < end) {
        int s = g_csr[j];
        float v = __ldg(&el[s * NH + head]) + erh;
        v = v > 0.f ? v : 0.2f * v;
        float a = __expf(v);
        float4 hv = ((const float4*)h)[s * 32 + lane];
        zA += a;
        accA.x = fmaf(a, hv.x, accA.x);
        accA.y = fmaf(a, hv.y, accA.y);
        accA.z = fmaf(a, hv.z, accA.z);
        accA.w = fmaf(a, hv.w, accA.w);
    }

    float z = zA + zB;
    float4 acc = make_float4(accA.x + accB.x, accA.y + accB.y,
                             accA.z + accB.z, accA.w + accB.w);
    float invz = (end > beg) ? 1.0f / z : 0.f;   // deg-0 -> output 0 (matches ref)
    acc.x *= invz; acc.y *= invz; acc.z *= invz; acc.w *= invz;

    if (act) {
        acc.x = acc.x > 0.f ? acc.x : 0.01f * acc.x;
        acc.y = acc.y > 0.f ? acc.y : 0.01f * acc.y;
        acc.z = acc.z > 0.f ? acc.z : 0.01f * acc.z;
        acc.w = acc.w > 0.f ? acc.w : 0.01f * acc.w;
    }
    ((float4*)out)[w * 32 + lane] = acc;
}

// ---------------- launch ----------------
// Two-stream graph: CSR build (src/dst only) runs concurrent with layer-1
// compute; join before agg1. wsplit2 overlaps agg1 on the side stream.
extern "C" void kernel_launch(void* const* d_in, const int* in_sizes, int n_in,
                              void* d_out, int out_size) {
    const float* x   = (const float*)d_in[0];
    const int*   src = (const int*)d_in[1];
    const int*   dst = (const int*)d_in[2];
    const float* W1  = (const float*)d_in[3];
    const float* al1 = (const float*)d_in[4];
    const float* ar1 = (const float*)d_in[5];
    const float* W2  = (const float*)d_in[6];
    const float* al2 = (const float*)d_in[7];
    const float* ar2 = (const float*)d_in[8];
    float* out = (float*)d_out;
    int E = in_sizes[1];

    float *ph, *po, *pel, *per;
    uint32_t *pwt;
    cudaGetSymbolAddress((void**)&ph,  g_h);
    cudaGetSymbolAddress((void**)&po,  g_o);
    cudaGetSymbolAddress((void**)&pel, g_el);
    cudaGetSymbolAddress((void**)&per, g_er);
    cudaGetSymbolAddress((void**)&pwt, g_wt);

    // one-time host-side resources (no device memory involved)
    static cudaStream_t s2 = nullptr;
    static cudaEvent_t ev_fork = nullptr, ev_csr = nullptr,
                       ev_gemm1 = nullptr, ev_w2 = nullptr;
    if (s2 == nullptr) {
        cudaStreamCreateWithFlags(&s2, cudaStreamNonBlocking);
        cudaEventCreateWithFlags(&ev_fork,  cudaEventDisableTiming);
        cudaEventCreateWithFlags(&ev_csr,   cudaEventDisableTiming);
        cudaEventCreateWithFlags(&ev_gemm1, cudaEventDisableTiming);
        cudaEventCreateWithFlags(&ev_w2,    cudaEventDisableTiming);
    }

    const int GB = (NN + 63) / 64;   // gemm blocks

    // fork: side stream joins the capture via event on the origin stream
    cudaEventRecord(ev_fork, 0);
    cudaStreamWaitEvent(s2, ev_fork, 0);

    // side stream: CSR build chain (independent of layer-1 compute)
    hist_kernel<<<(E + 255) / 256, 256, 0, s2>>>(dst, E);
    partial_scan_kernel<<<NB, 256, 0, s2>>>();
    scan_bsum_kernel<<<1, 32, 0, s2>>>();
    finalize_kernel<<<(NN + 255) / 256, 256, 0, s2>>>();
    scatter_kernel<<<(E + 255) / 256, 256, 0, s2>>>(src, dst, E);
    cudaEventRecord(ev_csr, s2);

    // main stream: layer-1 compute
    w_split_kernel<<<32, 256>>>(W1, pwt);
    gemm_mma<<<GB, 256>>>(x, pwt, ph);
    cudaEventRecord(ev_gemm1, 0);            // g_wt free after gemm1
    attn_proj<<<(NN + 7) / 8, 256>>>(ph, al1, ar1, pel, per);

    // side stream: wsplit2 overlaps agg1 (needs gemm1 done + CSR chain order)
    cudaStreamWaitEvent(s2, ev_gemm1, 0);
    w_split_kernel<<<32, 256, 0, s2>>>(W2, pwt);
    cudaEventRecord(ev_w2, s2);

    // join: agg1 needs the CSR
    cudaStreamWaitEvent(0, ev_csr, 0);
    agg_kernel<<<NN / 8, 256>>>(ph, pel, per, po, 1);

    // layer 2 (needs wsplit2)
    cudaStreamWaitEvent(0, ev_w2, 0);
    gemm_mma<<<GB, 256>>>(po, pwt, ph);
    attn_proj<<<(NN + 7) / 8, 256>>>(ph, al2, ar2, pel, per);
    agg_kernel<<<NN / 8, 256>>>(ph, pel, per, out, 0);
}

// round 12
// speedup vs baseline: 1.7423x; 1.0230x over previous
#include <cuda_runtime.h>
#include <cuda_bf16.h>
#include <stdint.h>

#define NN 50000
#define EE 800000
#define DH 128
#define NH 8
#define SCAN_CHUNK 2048
#define NB ((NN + SCAN_CHUNK - 1) / SCAN_CHUNK)   // 25 scan blocks

// ---------------- device scratch (no cudaMalloc allowed) ----------------
__device__ float    g_h[NN * DH];     // per-layer projected features h = x@W
__device__ float    g_o[NN * DH];     // layer-1 output (activated)
__device__ float    g_el[NN * NH];    // attention left logits
__device__ float    g_er[NN * NH];    // attention right logits
__device__ int      g_off[NN + 1];    // CSR row offsets (by dst)
__device__ int      g_cur[NN];        // scatter cursors
__device__ int      g_cnt[NN];        // in-degree histogram
__device__ int      g_csr[EE];        // src node per CSR slot
__device__ int      g_bsum[NB];
__device__ int      g_bbase[NB + 1];
// W split to bf16 hi/lo, fragment-layout chunk-major (see w_split_kernel)
__device__ uint32_t g_wt[128 * 128];  // 16384 u32 = 64KB

// ---------------- bf16 helpers ----------------
__device__ __forceinline__ uint32_t pack_bf16(float a, float b) {
    __nv_bfloat162 t = __floats2bfloat162_rn(a, b);
    return *(uint32_t*)&t;
}
__device__ __forceinline__ float bf16_hi(float v) {
    return __bfloat162float(__float2bfloat16_rn(v));
}
// D += A(16x16) * B(16x8), bf16 inputs, f32 accum
__device__ __forceinline__ void mma_bf16(float* c, const uint32_t* a,
                                         uint32_t b0, uint32_t b1) {
    asm("mma.sync.aligned.m16n8k16.row.col.f32.bf16.bf16.f32 "
        "{%0,%1,%2,%3}, {%4,%5,%6,%7}, {%8,%9}, {%0,%1,%2,%3};"
        : "+f"(c[0]), "+f"(c[1]), "+f"(c[2]), "+f"(c[3])
        : "r"(a[0]), "r"(a[1]), "r"(a[2]), "r"(a[3]), "r"(b0), "r"(b1));
}

// ---------------- W pre-split: fp32 -> bf16 hi/lo pairs, chunk-major ----------------
__global__ void w_split_kernel(const float* __restrict__ W, uint32_t* __restrict__ wt) {
    int i = blockIdx.x * 256 + threadIdx.x;   // 8192 pairs
    int c = (i >> 3) & 127;
    int kc = i >> 10;
    int p = i & 7;
    int k0 = kc * 16 + 2 * p;
    float v0 = W[k0 * 128 + c];
    float v1 = W[(k0 + 1) * 128 + c];
    float h0 = bf16_hi(v0), h1 = bf16_hi(v1);
    wt[i * 2]     = pack_bf16(h0, h1);
    wt[i * 2 + 1] = pack_bf16(v0 - h0, v1 - h1);
}

// ---------------- CSR build ----------------
__global__ void hist_kernel(const int* __restrict__ dst, int E) {
    int i = blockIdx.x * blockDim.x + threadIdx.x;
    if (i < E) atomicAdd(&g_cnt[dst[i]], 1);
}

__global__ __launch_bounds__(256) void partial_scan_kernel() {
    __shared__ int ws[8];
    int tid = threadIdx.x, lane = tid & 31, warp = tid >> 5;
    int base = blockIdx.x * SCAN_CHUNK + tid * 8;
    int v[8], s = 0;
    #pragma unroll
    for (int t = 0; t < 8; t++) {
        int i = base + t;
        v[t] = (i < NN) ? g_cnt[i] : 0;
        s += v[t];
    }
    int x = s;
    #pragma unroll
    for (int o = 1; o < 32; o <<= 1) {
        int y = __shfl_up_sync(0xffffffffu, x, o);
        if (lane >= o) x += y;
    }
    if (lane == 31) ws[warp] = x;
    __syncthreads();
    if (tid == 0) {
        int a = 0;
        #pragma unroll
        for (int w = 0; w < 8; w++) { int t = ws[w]; ws[w] = a; a += t; }
    }
    __syncthreads();
    int excl = ws[warp] + x - s;
    #pragma unroll
    for (int t = 0; t < 8; t++) {
        int i = base + t;
        if (i < NN) g_cnt[i] = excl;
        excl += v[t];
    }
    if (tid == 255) g_bsum[blockIdx.x] = ws[7] + x;
}

__global__ void scan_bsum_kernel() {
    int tid = threadIdx.x;
    int v = (tid < NB) ? g_bsum[tid] : 0;
    int x = v;
    #pragma unroll
    for (int o = 1; o < 32; o <<= 1) {
        int y = __shfl_up_sync(0xffffffffu, x, o);
        if (tid >= o) x += y;
    }
    if (tid < NB) g_bbase[tid] = x - v;
    if (tid == 31) g_bbase[NB] = x;
}

__global__ void finalize_kernel() {
    int i = blockIdx.x * blockDim.x + threadIdx.x;
    if (i < NN) {
        int off = g_cnt[i] + g_bbase[i / SCAN_CHUNK];
        g_off[i] = off;
        g_cur[i] = off;
        g_cnt[i] = 0;
    }
    if (i == 0) g_off[NN] = g_bbase[NB];
}

__global__ void scatter_kernel(const int* __restrict__ src,
                               const int* __restrict__ dst, int E) {
    int i = blockIdx.x * blockDim.x + threadIdx.x;
    if (i < E) {
        int p = atomicAdd(&g_cur[dst[i]], 1);
        g_csr[p] = src[i];
    }
}

// ---------------- GEMM via bf16 mma (3xBF16) + fused attn projections ----------------
// h[64 rows/block][128] = x@W; el/er computed in-epilogue (each warp's 32-col
// quarter = 2 whole heads; reduce over the 4 lanes sharing a row).
// Double-buffered smem chunks: prefetch kc+1 to regs, compute kc, store, 1 sync/iter.
__global__ __launch_bounds__(256) void gemm_mma(
    const float* __restrict__ x, const uint32_t* __restrict__ wt,
    const float* __restrict__ al, const float* __restrict__ ar,
    float* __restrict__ h, float* __restrict__ el, float* __restrict__ er) {
    __shared__ uint32_t xs[2 * 64 * 24];    // 12KB: row stride 12 u64
    __shared__ uint32_t ws[2 * 128 * 24];   // 24KB: col stride 12 u64
    int tid = threadIdx.x, lane = tid & 31, warp = tid >> 5;
    int g = lane >> 2, t = lane & 3;
    int row0 = blockIdx.x * 64;
    int mh = (warp & 1) * 32;        // m-half
    int nq = (warp >> 1) * 32;       // n-quarter (2 heads)
    int xr = tid >> 2, xq = tid & 3; // x-fill coords

    float c[2][4][4];
    #pragma unroll
    for (int mi = 0; mi < 2; mi++)
        #pragma unroll
        for (int j = 0; j < 4; j++)
            #pragma unroll
            for (int q = 0; q < 4; q++) c[mi][j][q] = 0.f;

    // prologue: fill buffer 0 with chunk 0
    {
        float4 v = make_float4(0.f, 0.f, 0.f, 0.f);
        if (row0 + xr < NN) v = ((const float4*)x)[(row0 + xr) * 32 + xq];
        float hx = bf16_hi(v.x), hy = bf16_hi(v.y);
        float hz = bf16_hi(v.z), hw = bf16_hi(v.w);
        uint4 o;
        o.x = pack_bf16(hx, hy);
        o.y = pack_bf16(v.x - hx, v.y - hy);
        o.z = pack_bf16(hz, hw);
        o.w = pack_bf16(v.z - hz, v.w - hw);
        ((uint4*)xs)[xr * 6 + xq] = o;
        #pragma unroll
        for (int e = 0; e < 2; e++) {
            int i = tid + e * 256;
            uint4 wv = ((const uint4*)wt)[i];
            ((uint4*)ws)[(i >> 2) * 6 + (i & 3)] = wv;
        }
    }

    for (int kc = 0; kc < 8; kc++) {
        __syncthreads();
        int cur = kc & 1, nxt = cur ^ 1;
        const uint2* xs2 = (const uint2*)xs + cur * 768;
        const uint2* ws2 = (const uint2*)ws + cur * 1536;

        // prefetch next chunk to registers
        float4 xv_n = make_float4(0.f, 0.f, 0.f, 0.f);
        uint4 wv0_n, wv1_n;
        if (kc < 7) {
            if (row0 + xr < NN)
                xv_n = ((const float4*)x)[(row0 + xr) * 32 + (kc + 1) * 4 + xq];
            wv0_n = ((const uint4*)(wt + (kc + 1) * 2048))[tid];
            wv1_n = ((const uint4*)(wt + (kc + 1) * 2048))[tid + 256];
        }

        // fragment loads + mma on current buffer
        uint32_t ah[2][4], al_[2][4];
        #pragma unroll
        for (int mi = 0; mi < 2; mi++) {
            int mb = (mh + mi * 16 + g) * 12;
            uint2 v0 = xs2[mb + t];
            uint2 v1 = xs2[mb + 96 + t];
            uint2 v2 = xs2[mb + 4 + t];
            uint2 v3 = xs2[mb + 100 + t];
            ah[mi][0] = v0.x; al_[mi][0] = v0.y;
            ah[mi][1] = v1.x; al_[mi][1] = v1.y;
            ah[mi][2] = v2.x; al_[mi][2] = v2.y;
            ah[mi][3] = v3.x; al_[mi][3] = v3.y;
        }
        #pragma unroll
        for (int j = 0; j < 4; j++) {
            int cb = (nq + j * 8 + g) * 12;
            uint2 b0 = ws2[cb + t];
            uint2 b1 = ws2[cb + 4 + t];
            #pragma unroll
            for (int mi = 0; mi < 2; mi++) {
                mma_bf16(c[mi][j], ah[mi],  b0.x, b1.x);   // hi*hi
                mma_bf16(c[mi][j], al_[mi], b0.x, b1.x);   // lo*hi
                mma_bf16(c[mi][j], ah[mi],  b0.y, b1.y);   // hi*lo
            }
        }

        // store prefetched chunk to the other buffer
        if (kc < 7) {
            float hx = bf16_hi(xv_n.x), hy = bf16_hi(xv_n.y);
            float hz = bf16_hi(xv_n.z), hw = bf16_hi(xv_n.w);
            uint4 o;
            o.x = pack_bf16(hx, hy);
            o.y = pack_bf16(xv_n.x - hx, xv_n.y - hy);
            o.z = pack_bf16(hz, hw);
            o.w = pack_bf16(xv_n.z - hz, xv_n.w - hw);
            ((uint4*)xs)[nxt * 384 + xr * 6 + xq] = o;
            ((uint4*)ws)[nxt * 768 + (tid >> 2) * 6 + (tid & 3)] = wv0_n;
            {
                int i = tid + 256;
                ((uint4*)ws)[nxt * 768 + (i >> 2) * 6 + (i & 3)] = wv1_n;
            }
        }
    }

    // epilogue: write h
    #pragma unroll
    for (int mi = 0; mi < 2; mi++)
        #pragma unroll
        for (int j = 0; j < 4; j++) {
            int col = nq + j * 8 + 2 * t;
            int r0 = row0 + mh + mi * 16 + g;
            if (r0 < NN)
                *(float2*)&h[r0 * DH + col] = make_float2(c[mi][j][0], c[mi][j][1]);
            if (r0 + 8 < NN)
                *(float2*)&h[(r0 + 8) * DH + col] = make_float2(c[mi][j][2], c[mi][j][3]);
        }

    // fused attn projections: el/er for this warp's 2 heads, 32 rows
    {
        const float2* alp = (const float2*)al;
        const float2* arp = (const float2*)ar;
        float2 a_l[4], a_r[4];
        #pragma unroll
        for (int j = 0; j < 4; j++) {
            a_l[j] = alp[(nq >> 1) + j * 4 + t];
            a_r[j] = arp[(nq >> 1) + j * 4 + t];
        }
        int head0 = nq >> 4;
        #pragma unroll
        for (int mi = 0; mi < 2; mi++) {
            float e[8];
            // el: [row g, head0], [row g, head1], [row g+8, head0], [row g+8, head1]
            e[0] = c[mi][0][0]*a_l[0].x + c[mi][0][1]*a_l[0].y + c[mi][1][0]*a_l[1].x + c[mi][1][1]*a_l[1].y;
            e[1] = c[mi][2][0]*a_l[2].x + c[mi][2][1]*a_l[2].y + c[mi][3][0]*a_l[3].x + c[mi][3][1]*a_l[3].y;
            e[2] = c[mi][0][2]*a_l[0].x + c[mi][0][3]*a_l[0].y + c[mi][1][2]*a_l[1].x + c[mi][1][3]*a_l[1].y;
            e[3] = c[mi][2][2]*a_l[2].x + c[mi][2][3]*a_l[2].y + c[mi][3][2]*a_l[3].x + c[mi][3][3]*a_l[3].y;
            // er: same rows/heads
            e[4] = c[mi][0][0]*a_r[0].x + c[mi][0][1]*a_r[0].y + c[mi][1][0]*a_r[1].x + c[mi][1][1]*a_r[1].y;
            e[5] = c[mi][2][0]*a_r[2].x + c[mi][2][1]*a_r[2].y + c[mi][3][0]*a_r[3].x + c[mi][3][1]*a_r[3].y;
            e[6] = c[mi][0][2]*a_r[0].x + c[mi][0][3]*a_r[0].y + c[mi][1][2]*a_r[1].x + c[mi][1][3]*a_r[1].y;
            e[7] = c[mi][2][2]*a_r[2].x + c[mi][2][3]*a_r[2].y + c[mi][3][2]*a_r[3].x + c[mi][3][3]*a_r[3].y;
            #pragma unroll
            for (int q = 0; q < 8; q++) {
                e[q] += __shfl_xor_sync(0xffffffffu, e[q], 1);
                e[q] += __shfl_xor_sync(0xffffffffu, e[q], 2);
            }
            if (t == 0) {
                int r0 = row0 + mh + mi * 16 + g;
                if (r0 < NN) {
                    el[r0 * NH + head0]     = e[0];
                    el[r0 * NH + head0 + 1] = e[1];
                    er[r0 * NH + head0]     = e[4];
                    er[r0 * NH + head0 + 1] = e[5];
                }
                if (r0 + 8 < NN) {
                    el[(r0 + 8) * NH + head0]     = e[2];
                    el[(r0 + 8) * NH + head0 + 1] = e[3];
                    er[(r0 + 8) * NH + head0]     = e[6];
                    er[(r0 + 8) * NH + head0 + 1] = e[7];
                }
            }
        }
    }
}

// ---------------- fused edge softmax + aggregation: one warp per dst node ----------------
__global__ __launch_bounds__(256) void agg_kernel(
    const float* __restrict__ h, const float* __restrict__ el,
    const float* __restrict__ er, float* __restrict__ out, int act) {
    int w = blockIdx.x * 8 + (threadIdx.x >> 5);
    if (w >= NN) return;
    int lane = threadIdx.x & 31;
    int head = lane >> 2;
    int beg = g_off[w], end = g_off[w + 1];

    float erh = __ldg(&er[w * NH + head]);

    float4 accA = make_float4(0.f, 0.f, 0.f, 0.f);
    float4 accB = make_float4(0.f, 0.f, 0.f, 0.f);
    float zA = 0.f, zB = 0.f;

    int j = beg;
    for (; j + 1 < end; j += 2) {
        int sA = g_csr[j];
        int sB = g_csr[j + 1];
        float vA = __ldg(&el[sA * NH + head]) + erh;
        float vB = __ldg(&el[sB * NH + head]) + erh;
        vA = vA > 0.f ? vA : 0.2f * vA;
        vB = vB > 0.f ? vB : 0.2f * vB;
        float aA = __expf(vA);
        float aB = __expf(vB);
        float4 hA = ((const float4*)h)[sA * 32 + lane];
        float4 hB = ((const float4*)h)[sB * 32 + lane];
        zA += aA;
        zB += aB;
        accA.x = fmaf(aA, hA.x, accA.x);
        accA.y = fmaf(aA, hA.y, accA.y);
        accA.z = fmaf(aA, hA.z, accA.z);
        accA.w = fmaf(aA, hA.w, accA.w);
        accB.x = fmaf(aB, hB.x, accB.x);
        accB.y = fmaf(aB, hB.y, accB.y);
        accB.z = fmaf(aB, hB.z, accB.z);
        accB.w = fmaf(aB, hB.w, accB.w);
    }
    if (j < end) {
        int s = g_csr[j];
        float v = __ldg(&el[s * NH + head]) + erh;
        v = v > 0.f ? v : 0.2f * v;
        float a = __expf(v);
        float4 hv = ((const float4*)h)[s * 32 + lane];
        zA += a;
        accA.x = fmaf(a, hv.x, accA.x);
        accA.y = fmaf(a, hv.y, accA.y);
        accA.z = fmaf(a, hv.z, accA.z);
        accA.w = fmaf(a, hv.w, accA.w);
    }

    float z = zA + zB;
    float4 acc = make_float4(accA.x + accB.x, accA.y + accB.y,
                             accA.z + accB.z, accA.w + accB.w);
    float invz = (end > beg) ? 1.0f / z : 0.f;   // deg-0 -> output 0 (matches ref)
    acc.x *= invz; acc.y *= invz; acc.z *= invz; acc.w *= invz;

    if (act) {
        acc.x = acc.x > 0.f ? acc.x : 0.01f * acc.x;
        acc.y = acc.y > 0.f ? acc.y : 0.01f * acc.y;
        acc.z = acc.z > 0.f ? acc.z : 0.01f * acc.z;
        acc.w = acc.w > 0.f ? acc.w : 0.01f * acc.w;
    }
    ((float4*)out)[w * 32 + lane] = acc;
}

// ---------------- launch ----------------
// Two-stream graph (CSR chain || layer-1 compute). API submission order is
// interleaved so gemm1 is my 4th launch -> ncu -s 5 captures it.
extern "C" void kernel_launch(void* const* d_in, const int* in_sizes, int n_in,
                              void* d_out, int out_size) {
    const float* x   = (const float*)d_in[0];
    const int*   src = (const int*)d_in[1];
    const int*   dst = (const int*)d_in[2];
    const float* W1  = (const float*)d_in[3];
    const float* al1 = (const float*)d_in[4];
    const float* ar1 = (const float*)d_in[5];
    const float* W2  = (const float*)d_in[6];
    const float* al2 = (const float*)d_in[7];
    const float* ar2 = (const float*)d_in[8];
    float* out = (float*)d_out;
    int E = in_sizes[1];

    float *ph, *po, *pel, *per;
    uint32_t *pwt;
    cudaGetSymbolAddress((void**)&ph,  g_h);
    cudaGetSymbolAddress((void**)&po,  g_o);
    cudaGetSymbolAddress((void**)&pel, g_el);
    cudaGetSymbolAddress((void**)&per, g_er);
    cudaGetSymbolAddress((void**)&pwt, g_wt);

    // one-time host-side resources (no device memory involved)
    static cudaStream_t s2 = nullptr;
    static cudaEvent_t ev_fork = nullptr, ev_csr = nullptr,
                       ev_gemm1 = nullptr, ev_w2 = nullptr;
    if (s2 == nullptr) {
        cudaStreamCreateWithFlags(&s2, cudaStreamNonBlocking);
        cudaEventCreateWithFlags(&ev_fork,  cudaEventDisableTiming);
        cudaEventCreateWithFlags(&ev_csr,   cudaEventDisableTiming);
        cudaEventCreateWithFlags(&ev_gemm1, cudaEventDisableTiming);
        cudaEventCreateWithFlags(&ev_w2,    cudaEventDisableTiming);
    }

    const int GB = (NN + 63) / 64;   // gemm blocks

    cudaEventRecord(ev_fork, 0);
    cudaStreamWaitEvent(s2, ev_fork, 0);

    w_split_kernel<<<32, 256>>>(W1, pwt);                                   // 0 main
    hist_kernel<<<(E + 255) / 256, 256, 0, s2>>>(dst, E);                   // 1 s2
    partial_scan_kernel<<<NB, 256, 0, s2>>>();                              // 2 s2
    gemm_mma<<<GB, 256>>>(x, pwt, al1, ar1, ph, pel, per);                  // 3 main (ncu)
    scan_bsum_kernel<<<1, 32, 0, s2>>>();                                   // 4 s2
    finalize_kernel<<<(NN + 255) / 256, 256, 0, s2>>>();                    // 5 s2
    scatter_kernel<<<(E + 255) / 256, 256, 0, s2>>>(src, dst, E);           // 6 s2
    cudaEventRecord(ev_csr, s2);
    cudaEventRecord(ev_gemm1, 0);

    // wsplit2 on side stream after gemm1 releases g_wt
    cudaStreamWaitEvent(s2, ev_gemm1, 0);
    w_split_kernel<<<32, 256, 0, s2>>>(W2, pwt);                            // 7 s2
    cudaEventRecord(ev_w2, s2);

    // join: agg1 needs the CSR (and gemm1, same stream)
    cudaStreamWaitEvent(0, ev_csr, 0);
    agg_kernel<<<NN / 8, 256>>>(ph, pel, per, po, 1);                       // 8 main

    // layer 2
    cudaStreamWaitEvent(0, ev_w2, 0);
    gemm_mma<<<GB, 256>>>(po, pwt, al2, ar2, ph, pel, per);                 // 9 main
    agg_kernel<<<NN / 8, 256>>>(ph, pel, per, out, 0);                      // 10 main
}